// round 2
// baseline (speedup 1.0000x reference)
#include <cuda_runtime.h>
#include <math.h>
#include <math_constants.h>

#define T_SEQ   2048
#define D_MODEL 4096
#define NH      32
#define NKV     8
#define HD      128
// G = NH/NKV = 4

// ---------------- scratch (device globals; no allocations allowed) ----------------
__device__ float g_Q[T_SEQ * NH * HD];   // [t][h*128+d]
__device__ float g_K[T_SEQ * NKV * HD];  // [t][kv*128+d]
__device__ float g_V[T_SEQ * NKV * HD];
__device__ float g_O[T_SEQ * NH * HD];   // attention output, [t][h*128+d]

// ---------------- fp32 tiled SGEMM: C[M,N] = A[M,K] @ B[K,N] (both row-major) ----------------
__global__ __launch_bounds__(256) void sgemm_kernel(const float* __restrict__ A,
                                                    const float* __restrict__ B,
                                                    float* __restrict__ C,
                                                    int M, int N, int K)
{
    __shared__ float As[8][128];   // [kk][row]  (A transposed into smem)
    __shared__ float Bs[8][128];   // [kk][col]

    const int tid = threadIdx.x;
    const int tx = tid & 15;       // 0..15 -> 8 cols each
    const int ty = tid >> 4;       // 0..15 -> 8 rows each
    const int row0 = blockIdx.y * 128;
    const int col0 = blockIdx.x * 128;

    const int arow = tid >> 1;          // 0..127
    const int acol = (tid & 1) * 4;     // 0 or 4
    const int brow = tid >> 5;          // 0..7
    const int bcol = (tid & 31) * 4;    // 0..124

    float acc[8][8];
#pragma unroll
    for (int i = 0; i < 8; i++)
#pragma unroll
        for (int j = 0; j < 8; j++) acc[i][j] = 0.0f;

    for (int k0 = 0; k0 < K; k0 += 8) {
        float4 a = *(const float4*)(A + (size_t)(row0 + arow) * K + k0 + acol);
        As[acol + 0][arow] = a.x;
        As[acol + 1][arow] = a.y;
        As[acol + 2][arow] = a.z;
        As[acol + 3][arow] = a.w;
        float4 b = *(const float4*)(B + (size_t)(k0 + brow) * N + col0 + bcol);
        *(float4*)&Bs[brow][bcol] = b;
        __syncthreads();

#pragma unroll
        for (int kk = 0; kk < 8; kk++) {
            float4 ra0 = *(float4*)&As[kk][ty * 8];
            float4 ra1 = *(float4*)&As[kk][ty * 8 + 4];
            float4 rb0 = *(float4*)&Bs[kk][tx * 8];
            float4 rb1 = *(float4*)&Bs[kk][tx * 8 + 4];
            float ra[8] = {ra0.x, ra0.y, ra0.z, ra0.w, ra1.x, ra1.y, ra1.z, ra1.w};
            float rb[8] = {rb0.x, rb0.y, rb0.z, rb0.w, rb1.x, rb1.y, rb1.z, rb1.w};
#pragma unroll
            for (int i = 0; i < 8; i++)
#pragma unroll
                for (int j = 0; j < 8; j++)
                    acc[i][j] += ra[i] * rb[j];
        }
        __syncthreads();
    }

#pragma unroll
    for (int i = 0; i < 8; i++) {
        float* cp = C + (size_t)(row0 + ty * 8 + i) * N + col0 + tx * 8;
        *(float4*)cp       = make_float4(acc[i][0], acc[i][1], acc[i][2], acc[i][3]);
        *(float4*)(cp + 4) = make_float4(acc[i][4], acc[i][5], acc[i][6], acc[i][7]);
    }
}

// ---------------- fused per-head RMSNorm + RoPE (in-place on g_Q / g_K) ----------------
// grid: (T_SEQ, NH + NKV); block: 128 threads (one per head-dim element)
__global__ __launch_bounds__(128) void rmsnorm_rope_kernel(const float* __restrict__ q_w,
                                                           const float* __restrict__ k_w)
{
    const int t = blockIdx.x;
    const int hy = blockIdx.y;
    const int i = threadIdx.x;

    float* base;
    const float* w;
    if (hy < NH) { base = g_Q + (size_t)t * (NH * HD) + hy * HD;        w = q_w; }
    else         { base = g_K + (size_t)t * (NKV * HD) + (hy - NH) * HD; w = k_w; }

    float x = base[i];

    // block reduce sum of squares over 128 threads
    float v = x * x;
#pragma unroll
    for (int o = 16; o > 0; o >>= 1) v += __shfl_xor_sync(0xffffffffu, v, o);
    __shared__ float ws[4];
    const int lane = i & 31, wid = i >> 5;
    if (lane == 0) ws[wid] = v;
    __syncthreads();
    float sum = ws[0] + ws[1] + ws[2] + ws[3];

    float r = rsqrtf(sum * (1.0f / HD) + 1e-6f);
    float xn = w[i] * (x * r);

    __shared__ float sh[HD];
    sh[i] = xn;
    __syncthreads();

    const int j = i & 63;  // i % (HD/2)
    float inv_freq = 1.0f / powf(1000000.0f, (float)j * (1.0f / 64.0f));
    float ang = (float)t * inv_freq;   // fp32 product, matching reference rounding
    float c = cosf(ang), s = sinf(ang);
    float rot = (i < 64) ? -sh[i + 64] : sh[i - 64];
    base[i] = xn * c + rot * s;
}

// ---------------- causal flash attention, fp32 ----------------
// grid: (T/64, NH); block 256 threads. BM=BN=64.
// smem: Qs[128][64] (k-major), Ks[128][64] (k-major), Vs[64][128], Ps[64][64]
#define ATTN_SMEM ((128 * 64 + 128 * 64 + 64 * 128 + 64 * 64) * 4)

__global__ __launch_bounds__(256) void attn_kernel(const float* __restrict__ Q,
                                                   const float* __restrict__ K,
                                                   const float* __restrict__ V,
                                                   float* __restrict__ O)
{
    extern __shared__ float sm[];
    float* Qs = sm;                  // [k][row]  128*64
    float* Ks = Qs + 128 * 64;       // [k][col]  128*64
    float* Vs = Ks + 128 * 64;       // [row][d]  64*128
    float* Ps = Vs + 64 * 128;       // [row][col] 64*64

    const int tid = threadIdx.x;
    const int tx = tid & 15;   // S cols tx*4..+3 ; out cols tx*8..+7
    const int ty = tid >> 4;   // rows ty*4..+3
    const int qtile = blockIdx.x;
    const int h = blockIdx.y;
    const int q0 = qtile * 64;

    const float* Qp = Q + (size_t)q0 * (NH * HD) + h * HD;
    const float* Kp = K + (h >> 2) * HD;
    const float* Vp = V + (h >> 2) * HD;

    // load Q tile (transposed into k-major)
#pragma unroll
    for (int it = 0; it < 8; it++) {
        int e = (tid + it * 256) * 4;
        int row = e >> 7, k = e & 127;
        float4 vq = *(const float4*)(Qp + (size_t)row * (NH * HD) + k);
        Qs[(k + 0) * 64 + row] = vq.x;
        Qs[(k + 1) * 64 + row] = vq.y;
        Qs[(k + 2) * 64 + row] = vq.z;
        Qs[(k + 3) * 64 + row] = vq.w;
    }

    float acc[4][8];
#pragma unroll
    for (int i = 0; i < 4; i++)
#pragma unroll
        for (int c = 0; c < 8; c++) acc[i][c] = 0.0f;
    float m_i[4], l_i[4];
#pragma unroll
    for (int i = 0; i < 4; i++) { m_i[i] = -CUDART_INF_F; l_i[i] = 0.0f; }

    const float scale = 0.08838834764831845f;  // 1/sqrt(128)

    const int ntiles = qtile + 1;
    for (int kt = 0; kt < ntiles; kt++) {
        const int k0 = kt * 64;
        __syncthreads();  // previous iteration done reading Ks/Vs/Ps

        // load K tile (k-major) + V tile (row-major)
#pragma unroll
        for (int it = 0; it < 8; it++) {
            int e = (tid + it * 256) * 4;
            int row = e >> 7, k = e & 127;
            float4 kv = *(const float4*)(Kp + (size_t)(k0 + row) * (NKV * HD) + k);
            Ks[(k + 0) * 64 + row] = kv.x;
            Ks[(k + 1) * 64 + row] = kv.y;
            Ks[(k + 2) * 64 + row] = kv.z;
            Ks[(k + 3) * 64 + row] = kv.w;
            float4 vv = *(const float4*)(Vp + (size_t)(k0 + row) * (NKV * HD) + k);
            *(float4*)&Vs[row * 128 + k] = vv;
        }
        __syncthreads();

        // S = Q K^T  (per-thread 4x4)
        float s[4][4];
#pragma unroll
        for (int i = 0; i < 4; i++)
#pragma unroll
            for (int j = 0; j < 4; j++) s[i][j] = 0.0f;

#pragma unroll 4
        for (int k = 0; k < 128; k++) {
            float4 qv = *(float4*)&Qs[k * 64 + ty * 4];
            float4 kv = *(float4*)&Ks[k * 64 + tx * 4];
            float qa[4] = {qv.x, qv.y, qv.z, qv.w};
            float ka[4] = {kv.x, kv.y, kv.z, kv.w};
#pragma unroll
            for (int i = 0; i < 4; i++)
#pragma unroll
                for (int j = 0; j < 4; j++)
                    s[i][j] += qa[i] * ka[j];
        }

        const bool diag = (kt == qtile);
#pragma unroll
        for (int i = 0; i < 4; i++)
#pragma unroll
            for (int j = 0; j < 4; j++) {
                s[i][j] *= scale;
                if (diag && (k0 + tx * 4 + j) > (q0 + ty * 4 + i)) s[i][j] = -CUDART_INF_F;
            }

        // online softmax (row reductions across the 16 tx-threads of each row)
#pragma unroll
        for (int i = 0; i < 4; i++) {
            float tm = fmaxf(fmaxf(s[i][0], s[i][1]), fmaxf(s[i][2], s[i][3]));
#pragma unroll
            for (int o = 8; o > 0; o >>= 1) tm = fmaxf(tm, __shfl_xor_sync(0xffffffffu, tm, o));
            float mn = fmaxf(m_i[i], tm);
            float fac = __expf(m_i[i] - mn);
            if (m_i[i] == -CUDART_INF_F) fac = 0.0f;
            float ts = 0.0f;
#pragma unroll
            for (int j = 0; j < 4; j++) {
                float p = (s[i][j] == -CUDART_INF_F) ? 0.0f : expf(s[i][j] - mn);
                s[i][j] = p;
                ts += p;
            }
#pragma unroll
            for (int o = 8; o > 0; o >>= 1) ts += __shfl_xor_sync(0xffffffffu, ts, o);
            l_i[i] = l_i[i] * fac + ts;
            m_i[i] = mn;
#pragma unroll
            for (int c = 0; c < 8; c++) acc[i][c] *= fac;
        }

        // P -> smem
#pragma unroll
        for (int i = 0; i < 4; i++)
            *(float4*)&Ps[(ty * 4 + i) * 64 + tx * 4] = make_float4(s[i][0], s[i][1], s[i][2], s[i][3]);
        __syncthreads();

        // acc += P @ V
#pragma unroll 2
        for (int j = 0; j < 64; j++) {
            float p0 = Ps[(ty * 4 + 0) * 64 + j];
            float p1 = Ps[(ty * 4 + 1) * 64 + j];
            float p2 = Ps[(ty * 4 + 2) * 64 + j];
            float p3 = Ps[(ty * 4 + 3) * 64 + j];
            float4 va = *(float4*)&Vs[j * 128 + tx * 8];
            float4 vb = *(float4*)&Vs[j * 128 + tx * 8 + 4];
            float vv[8] = {va.x, va.y, va.z, va.w, vb.x, vb.y, vb.z, vb.w};
            float pp[4] = {p0, p1, p2, p3};
#pragma unroll
            for (int i = 0; i < 4; i++)
#pragma unroll
                for (int c = 0; c < 8; c++)
                    acc[i][c] += pp[i] * vv[c];
        }
    }

    // epilogue
    float* Op = O + (size_t)q0 * (NH * HD) + h * HD;
#pragma unroll
    for (int i = 0; i < 4; i++) {
        float inv = 1.0f / l_i[i];
        int row = ty * 4 + i;
        *(float4*)(Op + (size_t)row * (NH * HD) + tx * 8) =
            make_float4(acc[i][0] * inv, acc[i][1] * inv, acc[i][2] * inv, acc[i][3] * inv);
        *(float4*)(Op + (size_t)row * (NH * HD) + tx * 8 + 4) =
            make_float4(acc[i][4] * inv, acc[i][5] * inv, acc[i][6] * inv, acc[i][7] * inv);
    }
}

// ---------------- launcher ----------------
extern "C" void kernel_launch(void* const* d_in, const int* in_sizes, int n_in,
                              void* d_out, int out_size)
{
    const float* x  = (const float*)d_in[0];
    const float* Wq = (const float*)d_in[1];
    const float* Wk = (const float*)d_in[2];
    const float* Wv = (const float*)d_in[3];
    const float* Wo = (const float*)d_in[4];
    const float* qw = (const float*)d_in[5];
    const float* kw = (const float*)d_in[6];
    float* out = (float*)d_out;

    float *Qb, *Kb, *Vb, *Ob;
    cudaGetSymbolAddress((void**)&Qb, g_Q);
    cudaGetSymbolAddress((void**)&Kb, g_K);
    cudaGetSymbolAddress((void**)&Vb, g_V);
    cudaGetSymbolAddress((void**)&Ob, g_O);

    cudaFuncSetAttribute(attn_kernel, cudaFuncAttributeMaxDynamicSharedMemorySize, ATTN_SMEM);

    dim3 blk(256);
    // QKV projections
    sgemm_kernel<<<dim3(D_MODEL / 128, T_SEQ / 128), blk>>>(x, Wq, Qb, T_SEQ, NH * HD, D_MODEL);
    sgemm_kernel<<<dim3((NKV * HD) / 128, T_SEQ / 128), blk>>>(x, Wk, Kb, T_SEQ, NKV * HD, D_MODEL);
    sgemm_kernel<<<dim3((NKV * HD) / 128, T_SEQ / 128), blk>>>(x, Wv, Vb, T_SEQ, NKV * HD, D_MODEL);

    // RMSNorm + RoPE on Q and K (in place)
    rmsnorm_rope_kernel<<<dim3(T_SEQ, NH + NKV), 128>>>(qw, kw);

    // causal attention
    attn_kernel<<<dim3(T_SEQ / 64, NH), blk, ATTN_SMEM>>>(Qb, Kb, Vb, Ob);

    // output projection -> d_out
    sgemm_kernel<<<dim3(D_MODEL / 128, T_SEQ / 128), blk>>>(Ob, Wo, out, T_SEQ, D_MODEL, D_MODEL);
}

// round 6
// speedup vs baseline: 1.9178x; 1.9178x over previous
#include <cuda_runtime.h>
#include <cuda_bf16.h>
#include <math.h>
#include <math_constants.h>
#include <stdint.h>

#define T_SEQ   2048
#define D_MODEL 4096
#define NH      32
#define NKV     8
#define HD      128
#define NQ      (NH * HD)    // 4096
#define NKVD    (NKV * HD)   // 1024

// ---------------- scratch (device globals; no allocations allowed) ----------------
__device__ float g_Q[T_SEQ * NQ];
__device__ float g_K[T_SEQ * NKVD];
__device__ float g_V[T_SEQ * NKVD];
__device__ float g_O[T_SEQ * NQ];

__device__ __nv_bfloat16 g_Xhi[T_SEQ * D_MODEL];
__device__ __nv_bfloat16 g_Xlo[T_SEQ * D_MODEL];
__device__ __nv_bfloat16 g_Ohi[T_SEQ * NQ];
__device__ __nv_bfloat16 g_Olo[T_SEQ * NQ];
__device__ __nv_bfloat16 g_Wqt_hi[NQ * D_MODEL];
__device__ __nv_bfloat16 g_Wqt_lo[NQ * D_MODEL];
__device__ __nv_bfloat16 g_Wkt_hi[NKVD * D_MODEL];
__device__ __nv_bfloat16 g_Wkt_lo[NKVD * D_MODEL];
__device__ __nv_bfloat16 g_Wvt_hi[NKVD * D_MODEL];
__device__ __nv_bfloat16 g_Wvt_lo[NKVD * D_MODEL];
__device__ __nv_bfloat16 g_Wot_hi[D_MODEL * NQ];
__device__ __nv_bfloat16 g_Wot_lo[D_MODEL * NQ];

// ---------------- helpers ----------------
static __device__ __forceinline__ uint32_t smem_u32(const void* p) {
    uint32_t a;
    asm("{ .reg .u64 t; cvta.to.shared.u64 t, %1; cvt.u32.u64 %0, t; }" : "=r"(a) : "l"(p));
    return a;
}
static __device__ __forceinline__ void cp16(uint32_t s, const void* g) {
    asm volatile("cp.async.cg.shared.global [%0], [%1], 16;" :: "r"(s), "l"(g));
}

#define LDSM4(R, ADDR)                                                              \
    asm volatile("ldmatrix.sync.aligned.m8n8.x4.shared.b16 {%0,%1,%2,%3}, [%4];"    \
                 : "=r"((R)[0]), "=r"((R)[1]), "=r"((R)[2]), "=r"((R)[3])           \
                 : "r"(ADDR))

#define MMA16816(C, A, B0, B1)                                                      \
    asm volatile("mma.sync.aligned.m16n8k16.row.col.f32.bf16.bf16.f32 "             \
                 "{%0,%1,%2,%3}, {%4,%5,%6,%7}, {%8,%9}, {%0,%1,%2,%3};"            \
                 : "+f"((C)[0]), "+f"((C)[1]), "+f"((C)[2]), "+f"((C)[3])           \
                 : "r"((A)[0]), "r"((A)[1]), "r"((A)[2]), "r"((A)[3]),              \
                   "r"(B0), "r"(B1))

// ---------------- bf16 hi/lo split (elementwise) ----------------
__global__ __launch_bounds__(256) void split_kernel(const float4* __restrict__ x,
                                                    __nv_bfloat16* __restrict__ hi,
                                                    __nv_bfloat16* __restrict__ lo, int n4) {
    int i = blockIdx.x * 256 + threadIdx.x;
    if (i >= n4) return;
    float4 v = x[i];
    float vs[4] = {v.x, v.y, v.z, v.w};
    __nv_bfloat16 h[4], l[4];
#pragma unroll
    for (int j = 0; j < 4; j++) {
        h[j] = __float2bfloat16(vs[j]);
        l[j] = __float2bfloat16(vs[j] - __bfloat162float(h[j]));
    }
    __nv_bfloat162* hp = reinterpret_cast<__nv_bfloat162*>(hi) + 2 * (size_t)i;
    __nv_bfloat162* lp = reinterpret_cast<__nv_bfloat162*>(lo) + 2 * (size_t)i;
    hp[0] = __halves2bfloat162(h[0], h[1]);
    hp[1] = __halves2bfloat162(h[2], h[3]);
    lp[0] = __halves2bfloat162(l[0], l[1]);
    lp[1] = __halves2bfloat162(l[2], l[3]);
}

// ---------------- transpose + bf16 split: W[K][N] -> Wt_hi/lo[N][K] ----------------
__global__ __launch_bounds__(256) void tsplit_kernel(const float* __restrict__ W,
                                                     __nv_bfloat16* __restrict__ hi,
                                                     __nv_bfloat16* __restrict__ lo,
                                                     int K, int N) {
    __shared__ float t[32][33];
    int n0 = blockIdx.x * 32, k0 = blockIdx.y * 32;
    int tx = threadIdx.x & 31, ty = threadIdx.x >> 5;
#pragma unroll
    for (int i = 0; i < 4; i++)
        t[ty + i * 8][tx] = W[(size_t)(k0 + ty + i * 8) * N + n0 + tx];
    __syncthreads();
#pragma unroll
    for (int i = 0; i < 4; i++) {
        int n = n0 + ty + i * 8, k = k0 + tx;
        float v = t[tx][ty + i * 8];
        __nv_bfloat16 h = __float2bfloat16(v);
        hi[(size_t)n * K + k] = h;
        lo[(size_t)n * K + k] = __float2bfloat16(v - __bfloat162float(h));
    }
}

// ---------------- HMMA bf16-split GEMM ----------------
// C[M,N] = A[M,K] @ Bt[N,K]^T, A/Bt as bf16 hi/lo pairs (K-major), C fp32.
// CTA 128x128x32, 8 warps (warp tile 64x32). acc += Ah*Bh + Ah*Bl + Al*Bh.
#define GBM 128
#define GBN 128
#define GBK 32
#define SROW 80                 // 32 bf16 = 64B + 16B pad: conflict-free ldmatrix
#define SA_HI 0
#define SA_LO 10240
#define SB_HI 20480
#define SB_LO 30720
#define STAGE 40960
#define GEMM_SMEM (2 * STAGE)

__global__ __launch_bounds__(256, 1) void gemm_kernel(
    const __nv_bfloat16* __restrict__ Ahi, const __nv_bfloat16* __restrict__ Alo,
    const __nv_bfloat16* __restrict__ Bhi, const __nv_bfloat16* __restrict__ Blo,
    float* __restrict__ C, int M, int N, int Kd) {
    extern __shared__ char smem[];
    const uint32_t sb = smem_u32(smem);
    const int tid = threadIdx.x, lane = tid & 31, wid = tid >> 5;
    const int m0 = blockIdx.y * GBM, n0 = blockIdx.x * GBN;

    const int wm = (wid & 1) * 64;   // warp M offset
    const int wn = (wid >> 1) * 32;  // warp N offset

    // ldmatrix per-lane address offsets (bytes)
    const uint32_t a_ro = (uint32_t)(wm + (lane & 15)) * SROW + ((lane >> 4) * 16);
    const uint32_t b_ro = (uint32_t)(wn + ((lane >> 4) << 3) + (lane & 7)) * SROW + (((lane >> 3) & 1) * 16);

    float acc[4][4][4];
#pragma unroll
    for (int a = 0; a < 4; a++)
#pragma unroll
        for (int b = 0; b < 4; b++)
#pragma unroll
            for (int c = 0; c < 4; c++) acc[a][b][c] = 0.0f;

    const int NC = Kd / GBK;

    auto stage_load = [&](int c, int st) {
        uint32_t s0 = sb + st * STAGE;
        int k0 = c * GBK;
#pragma unroll
        for (int i = 0; i < 2; i++) {
            int idx = tid + i * 256;       // 0..511
            int r = idx >> 2, seg = idx & 3;
            uint32_t so = (uint32_t)(r * SROW + seg * 16);
            const char* ga = (const char*)(Ahi + (size_t)(m0 + r) * Kd + k0) + seg * 16;
            const char* gal = (const char*)(Alo + (size_t)(m0 + r) * Kd + k0) + seg * 16;
            const char* gb = (const char*)(Bhi + (size_t)(n0 + r) * Kd + k0) + seg * 16;
            const char* gbl = (const char*)(Blo + (size_t)(n0 + r) * Kd + k0) + seg * 16;
            cp16(s0 + SA_HI + so, ga);
            cp16(s0 + SA_LO + so, gal);
            cp16(s0 + SB_HI + so, gb);
            cp16(s0 + SB_LO + so, gbl);
        }
        asm volatile("cp.async.commit_group;" ::: "memory");
    };

    stage_load(0, 0);

    for (int c = 0; c < NC; ++c) {
        if (c + 1 < NC) {
            stage_load(c + 1, (c + 1) & 1);
            asm volatile("cp.async.wait_group 1;" ::: "memory");
        } else {
            asm volatile("cp.async.wait_group 0;" ::: "memory");
        }
        __syncthreads();

        const uint32_t s0 = sb + (c & 1) * STAGE;
#pragma unroll
        for (int ks = 0; ks < 2; ks++) {
            uint32_t ah[4][4], al[4][4], bh[2][4], bl[2][4];
#pragma unroll
            for (int mf = 0; mf < 4; mf++) {
                uint32_t ao = a_ro + (uint32_t)(mf * 16) * SROW + ks * 32;
                LDSM4(ah[mf], s0 + SA_HI + ao);
                LDSM4(al[mf], s0 + SA_LO + ao);
            }
#pragma unroll
            for (int p = 0; p < 2; p++) {
                uint32_t bo = b_ro + (uint32_t)(p * 16) * SROW + ks * 32;
                LDSM4(bh[p], s0 + SB_HI + bo);
                LDSM4(bl[p], s0 + SB_LO + bo);
            }
#pragma unroll
            for (int mf = 0; mf < 4; mf++)
#pragma unroll
                for (int nf = 0; nf < 4; nf++) {
                    uint32_t h0 = bh[nf >> 1][(nf & 1) * 2], h1 = bh[nf >> 1][(nf & 1) * 2 + 1];
                    uint32_t l0 = bl[nf >> 1][(nf & 1) * 2], l1 = bl[nf >> 1][(nf & 1) * 2 + 1];
                    MMA16816(acc[mf][nf], ah[mf], h0, h1);
                    MMA16816(acc[mf][nf], ah[mf], l0, l1);
                    MMA16816(acc[mf][nf], al[mf], h0, h1);
                }
        }
        __syncthreads();
    }

    // epilogue: fragment layout -> C
    const int gid = lane >> 2, tig = lane & 3;
#pragma unroll
    for (int mf = 0; mf < 4; mf++)
#pragma unroll
        for (int nf = 0; nf < 4; nf++) {
            int row = m0 + wm + mf * 16 + gid;
            int col = n0 + wn + nf * 8 + tig * 2;
            float* cp0 = C + (size_t)row * N + col;
            float* cp1 = C + (size_t)(row + 8) * N + col;
            *(float2*)cp0 = make_float2(acc[mf][nf][0], acc[mf][nf][1]);
            *(float2*)cp1 = make_float2(acc[mf][nf][2], acc[mf][nf][3]);
        }
}

// ---------------- fused per-head RMSNorm + RoPE (in-place on g_Q / g_K) ----------------
__global__ __launch_bounds__(128) void rmsnorm_rope_kernel(const float* __restrict__ q_w,
                                                           const float* __restrict__ k_w) {
    const int t = blockIdx.x;
    const int hy = blockIdx.y;
    const int i = threadIdx.x;

    float* base;
    const float* w;
    if (hy < NH) { base = g_Q + (size_t)t * NQ + hy * HD;          w = q_w; }
    else         { base = g_K + (size_t)t * NKVD + (hy - NH) * HD; w = k_w; }

    float x = base[i];
    float v = x * x;
#pragma unroll
    for (int o = 16; o > 0; o >>= 1) v += __shfl_xor_sync(0xffffffffu, v, o);
    __shared__ float ws[4];
    const int lane = i & 31, wid = i >> 5;
    if (lane == 0) ws[wid] = v;
    __syncthreads();
    float sum = ws[0] + ws[1] + ws[2] + ws[3];

    float r = rsqrtf(sum * (1.0f / HD) + 1e-6f);
    float xn = w[i] * (x * r);

    __shared__ float sh[HD];
    sh[i] = xn;
    __syncthreads();

    const int j = i & 63;
    float inv_freq = 1.0f / powf(1000000.0f, (float)j * (1.0f / 64.0f));
    float ang = (float)t * inv_freq;
    float c = cosf(ang), s = sinf(ang);
    float rot = (i < 64) ? -sh[i + 64] : sh[i - 64];
    base[i] = xn * c + rot * s;
}

// ---------------- causal flash attention, fp32 ----------------
#define ATTN_SMEM ((128 * 64 + 128 * 64 + 64 * 128 + 64 * 64) * 4)

__global__ __launch_bounds__(256) void attn_kernel(const float* __restrict__ Q,
                                                   const float* __restrict__ K,
                                                   const float* __restrict__ V,
                                                   float* __restrict__ O) {
    extern __shared__ float sm[];
    float* Qs = sm;
    float* Ks = Qs + 128 * 64;
    float* Vs = Ks + 128 * 64;
    float* Ps = Vs + 64 * 128;

    const int tid = threadIdx.x;
    const int tx = tid & 15;
    const int ty = tid >> 4;
    const int qtile = blockIdx.x;
    const int h = blockIdx.y;
    const int q0 = qtile * 64;

    const float* Qp = Q + (size_t)q0 * NQ + h * HD;
    const float* Kp = K + (h >> 2) * HD;
    const float* Vp = V + (h >> 2) * HD;

#pragma unroll
    for (int it = 0; it < 8; it++) {
        int e = (tid + it * 256) * 4;
        int row = e >> 7, k = e & 127;
        float4 vq = *(const float4*)(Qp + (size_t)row * NQ + k);
        Qs[(k + 0) * 64 + row] = vq.x;
        Qs[(k + 1) * 64 + row] = vq.y;
        Qs[(k + 2) * 64 + row] = vq.z;
        Qs[(k + 3) * 64 + row] = vq.w;
    }

    float acc[4][8];
#pragma unroll
    for (int i = 0; i < 4; i++)
#pragma unroll
        for (int c = 0; c < 8; c++) acc[i][c] = 0.0f;
    float m_i[4], l_i[4];
#pragma unroll
    for (int i = 0; i < 4; i++) { m_i[i] = -CUDART_INF_F; l_i[i] = 0.0f; }

    const float scale = 0.08838834764831845f;

    const int ntiles = qtile + 1;
    for (int kt = 0; kt < ntiles; kt++) {
        const int k0 = kt * 64;
        __syncthreads();

#pragma unroll
        for (int it = 0; it < 8; it++) {
            int e = (tid + it * 256) * 4;
            int row = e >> 7, k = e & 127;
            float4 kv = *(const float4*)(Kp + (size_t)(k0 + row) * NKVD + k);
            Ks[(k + 0) * 64 + row] = kv.x;
            Ks[(k + 1) * 64 + row] = kv.y;
            Ks[(k + 2) * 64 + row] = kv.z;
            Ks[(k + 3) * 64 + row] = kv.w;
            float4 vv = *(const float4*)(Vp + (size_t)(k0 + row) * NKVD + k);
            *(float4*)&Vs[row * 128 + k] = vv;
        }
        __syncthreads();

        float s[4][4];
#pragma unroll
        for (int i = 0; i < 4; i++)
#pragma unroll
            for (int j = 0; j < 4; j++) s[i][j] = 0.0f;

#pragma unroll 4
        for (int k = 0; k < 128; k++) {
            float4 qv = *(float4*)&Qs[k * 64 + ty * 4];
            float4 kv = *(float4*)&Ks[k * 64 + tx * 4];
            float qa[4] = {qv.x, qv.y, qv.z, qv.w};
            float ka[4] = {kv.x, kv.y, kv.z, kv.w};
#pragma unroll
            for (int i = 0; i < 4; i++)
#pragma unroll
                for (int j = 0; j < 4; j++)
                    s[i][j] += qa[i] * ka[j];
        }

        const bool diag = (kt == qtile);
#pragma unroll
        for (int i = 0; i < 4; i++)
#pragma unroll
            for (int j = 0; j < 4; j++) {
                s[i][j] *= scale;
                if (diag && (k0 + tx * 4 + j) > (q0 + ty * 4 + i)) s[i][j] = -CUDART_INF_F;
            }

#pragma unroll
        for (int i = 0; i < 4; i++) {
            float tm = fmaxf(fmaxf(s[i][0], s[i][1]), fmaxf(s[i][2], s[i][3]));
#pragma unroll
            for (int o = 8; o > 0; o >>= 1) tm = fmaxf(tm, __shfl_xor_sync(0xffffffffu, tm, o));
            float mn = fmaxf(m_i[i], tm);
            float fac = __expf(m_i[i] - mn);
            if (m_i[i] == -CUDART_INF_F) fac = 0.0f;
            float ts = 0.0f;
#pragma unroll
            for (int j = 0; j < 4; j++) {
                float p = (s[i][j] == -CUDART_INF_F) ? 0.0f : expf(s[i][j] - mn);
                s[i][j] = p;
                ts += p;
            }
#pragma unroll
            for (int o = 8; o > 0; o >>= 1) ts += __shfl_xor_sync(0xffffffffu, ts, o);
            l_i[i] = l_i[i] * fac + ts;
            m_i[i] = mn;
#pragma unroll
            for (int c = 0; c < 8; c++) acc[i][c] *= fac;
        }

#pragma unroll
        for (int i = 0; i < 4; i++)
            *(float4*)&Ps[(ty * 4 + i) * 64 + tx * 4] = make_float4(s[i][0], s[i][1], s[i][2], s[i][3]);
        __syncthreads();

#pragma unroll 2
        for (int j = 0; j < 64; j++) {
            float p0 = Ps[(ty * 4 + 0) * 64 + j];
            float p1 = Ps[(ty * 4 + 1) * 64 + j];
            float p2 = Ps[(ty * 4 + 2) * 64 + j];
            float p3 = Ps[(ty * 4 + 3) * 64 + j];
            float4 va = *(float4*)&Vs[j * 128 + tx * 8];
            float4 vb = *(float4*)&Vs[j * 128 + tx * 8 + 4];
            float vv[8] = {va.x, va.y, va.z, va.w, vb.x, vb.y, vb.z, vb.w};
            float pp[4] = {p0, p1, p2, p3};
#pragma unroll
            for (int i = 0; i < 4; i++)
#pragma unroll
                for (int c = 0; c < 8; c++)
                    acc[i][c] += pp[i] * vv[c];
        }
    }

    float* Op = O + (size_t)q0 * NQ + h * HD;
#pragma unroll
    for (int i = 0; i < 4; i++) {
        float inv = 1.0f / l_i[i];
        int row = ty * 4 + i;
        *(float4*)(Op + (size_t)row * NQ + tx * 8) =
            make_float4(acc[i][0] * inv, acc[i][1] * inv, acc[i][2] * inv, acc[i][3] * inv);
        *(float4*)(Op + (size_t)row * NQ + tx * 8 + 4) =
            make_float4(acc[i][4] * inv, acc[i][5] * inv, acc[i][6] * inv, acc[i][7] * inv);
    }
}

// ---------------- launcher ----------------
extern "C" void kernel_launch(void* const* d_in, const int* in_sizes, int n_in,
                              void* d_out, int out_size) {
    const float* x  = (const float*)d_in[0];
    const float* Wq = (const float*)d_in[1];
    const float* Wk = (const float*)d_in[2];
    const float* Wv = (const float*)d_in[3];
    const float* Wo = (const float*)d_in[4];
    const float* qw = (const float*)d_in[5];
    const float* kw = (const float*)d_in[6];
    float* out = (float*)d_out;

    float *Qb, *Kb, *Vb, *Ob;
    cudaGetSymbolAddress((void**)&Qb, g_Q);
    cudaGetSymbolAddress((void**)&Kb, g_K);
    cudaGetSymbolAddress((void**)&Vb, g_V);
    cudaGetSymbolAddress((void**)&Ob, g_O);
    __nv_bfloat16 *Xhi, *Xlo, *Ohi, *Olo, *Wqh, *Wql, *Wkh, *Wkl, *Wvh, *Wvl, *Woh, *Wol;
    cudaGetSymbolAddress((void**)&Xhi, g_Xhi);
    cudaGetSymbolAddress((void**)&Xlo, g_Xlo);
    cudaGetSymbolAddress((void**)&Ohi, g_Ohi);
    cudaGetSymbolAddress((void**)&Olo, g_Olo);
    cudaGetSymbolAddress((void**)&Wqh, g_Wqt_hi);
    cudaGetSymbolAddress((void**)&Wql, g_Wqt_lo);
    cudaGetSymbolAddress((void**)&Wkh, g_Wkt_hi);
    cudaGetSymbolAddress((void**)&Wkl, g_Wkt_lo);
    cudaGetSymbolAddress((void**)&Wvh, g_Wvt_hi);
    cudaGetSymbolAddress((void**)&Wvl, g_Wvt_lo);
    cudaGetSymbolAddress((void**)&Woh, g_Wot_hi);
    cudaGetSymbolAddress((void**)&Wol, g_Wot_lo);

    cudaFuncSetAttribute(gemm_kernel, cudaFuncAttributeMaxDynamicSharedMemorySize, GEMM_SMEM);
    cudaFuncSetAttribute(attn_kernel, cudaFuncAttributeMaxDynamicSharedMemorySize, ATTN_SMEM);

    // 1. bf16 splits of X and transposed weights
    int n4x = T_SEQ * D_MODEL / 4;
    split_kernel<<<(n4x + 255) / 256, 256>>>((const float4*)x, Xhi, Xlo, n4x);
    tsplit_kernel<<<dim3(NQ / 32, D_MODEL / 32), 256>>>(Wq, Wqh, Wql, D_MODEL, NQ);
    tsplit_kernel<<<dim3(NKVD / 32, D_MODEL / 32), 256>>>(Wk, Wkh, Wkl, D_MODEL, NKVD);
    tsplit_kernel<<<dim3(NKVD / 32, D_MODEL / 32), 256>>>(Wv, Wvh, Wvl, D_MODEL, NKVD);
    tsplit_kernel<<<dim3(NQ / 32, D_MODEL / 32), 256>>>(Wo, Woh, Wol, NQ, D_MODEL);

    // 2. QKV projections (HMMA bf16-split)
    gemm_kernel<<<dim3(NQ / GBN, T_SEQ / GBM), 256, GEMM_SMEM>>>(Xhi, Xlo, Wqh, Wql, Qb, T_SEQ, NQ, D_MODEL);
    gemm_kernel<<<dim3(NKVD / GBN, T_SEQ / GBM), 256, GEMM_SMEM>>>(Xhi, Xlo, Wkh, Wkl, Kb, T_SEQ, NKVD, D_MODEL);
    gemm_kernel<<<dim3(NKVD / GBN, T_SEQ / GBM), 256, GEMM_SMEM>>>(Xhi, Xlo, Wvh, Wvl, Vb, T_SEQ, NKVD, D_MODEL);

    // 3. RMSNorm + RoPE
    rmsnorm_rope_kernel<<<dim3(T_SEQ, NH + NKV), 128>>>(qw, kw);

    // 4. causal attention
    attn_kernel<<<dim3(T_SEQ / 64, NH), 256, ATTN_SMEM>>>(Qb, Kb, Vb, Ob);

    // 5. output projection (HMMA bf16-split)
    int n4o = T_SEQ * NQ / 4;
    split_kernel<<<(n4o + 255) / 256, 256>>>((const float4*)Ob, Ohi, Olo, n4o);
    gemm_kernel<<<dim3(D_MODEL / GBN, T_SEQ / GBM), 256, GEMM_SMEM>>>(Ohi, Olo, Woh, Wol, out, T_SEQ, D_MODEL, NQ);
}

// round 7
// speedup vs baseline: 3.2886x; 1.7148x over previous
#include <cuda_runtime.h>
#include <cuda_bf16.h>
#include <math.h>
#include <math_constants.h>
#include <stdint.h>

#define T_SEQ   2048
#define D_MODEL 4096
#define NH      32
#define NKV     8
#define HD      128
#define NQ      (NH * HD)    // 4096
#define NKVD    (NKV * HD)   // 1024

// ---------------- scratch (device globals; no allocations allowed) ----------------
__device__ float g_Q[T_SEQ * NQ];       // fp32 Q projection output
__device__ float g_K[T_SEQ * NKVD];
__device__ float g_V[T_SEQ * NKVD];

__device__ __nv_bfloat16 g_Xhi[T_SEQ * D_MODEL];
__device__ __nv_bfloat16 g_Xlo[T_SEQ * D_MODEL];
__device__ __nv_bfloat16 g_Ohi[T_SEQ * NQ];
__device__ __nv_bfloat16 g_Olo[T_SEQ * NQ];
__device__ __nv_bfloat16 g_Qhi[T_SEQ * NQ];
__device__ __nv_bfloat16 g_Qlo[T_SEQ * NQ];
__device__ __nv_bfloat16 g_Khi[T_SEQ * NKVD];
__device__ __nv_bfloat16 g_Klo[T_SEQ * NKVD];
__device__ __nv_bfloat16 g_Vhi[T_SEQ * NKVD];
__device__ __nv_bfloat16 g_Vlo[T_SEQ * NKVD];
__device__ __nv_bfloat16 g_Wqt_hi[NQ * D_MODEL];
__device__ __nv_bfloat16 g_Wqt_lo[NQ * D_MODEL];
__device__ __nv_bfloat16 g_Wkt_hi[NKVD * D_MODEL];
__device__ __nv_bfloat16 g_Wkt_lo[NKVD * D_MODEL];
__device__ __nv_bfloat16 g_Wvt_hi[NKVD * D_MODEL];
__device__ __nv_bfloat16 g_Wvt_lo[NKVD * D_MODEL];
__device__ __nv_bfloat16 g_Wot_hi[D_MODEL * NQ];
__device__ __nv_bfloat16 g_Wot_lo[D_MODEL * NQ];

// ---------------- helpers ----------------
static __device__ __forceinline__ uint32_t smem_u32(const void* p) {
    uint32_t a;
    asm("{ .reg .u64 t; cvta.to.shared.u64 t, %1; cvt.u32.u64 %0, t; }" : "=r"(a) : "l"(p));
    return a;
}
static __device__ __forceinline__ void cp16(uint32_t s, const void* g) {
    asm volatile("cp.async.cg.shared.global [%0], [%1], 16;" :: "r"(s), "l"(g));
}
static __device__ __forceinline__ uint32_t pack_bf2(float a, float b) {
    __nv_bfloat162 t = __halves2bfloat162(__float2bfloat16(a), __float2bfloat16(b));
    return *(uint32_t*)&t;
}

#define LDSM4(R, ADDR)                                                              \
    asm volatile("ldmatrix.sync.aligned.m8n8.x4.shared.b16 {%0,%1,%2,%3}, [%4];"    \
                 : "=r"((R)[0]), "=r"((R)[1]), "=r"((R)[2]), "=r"((R)[3])           \
                 : "r"(ADDR))

#define LDSM4T(R, ADDR)                                                             \
    asm volatile("ldmatrix.sync.aligned.m8n8.x4.trans.shared.b16 {%0,%1,%2,%3}, [%4];" \
                 : "=r"((R)[0]), "=r"((R)[1]), "=r"((R)[2]), "=r"((R)[3])           \
                 : "r"(ADDR))

#define MMA16816(C, A, B0, B1)                                                      \
    asm volatile("mma.sync.aligned.m16n8k16.row.col.f32.bf16.bf16.f32 "             \
                 "{%0,%1,%2,%3}, {%4,%5,%6,%7}, {%8,%9}, {%0,%1,%2,%3};"            \
                 : "+f"((C)[0]), "+f"((C)[1]), "+f"((C)[2]), "+f"((C)[3])           \
                 : "r"((A)[0]), "r"((A)[1]), "r"((A)[2]), "r"((A)[3]),              \
                   "r"(B0), "r"(B1))

// ---------------- bf16 hi/lo split (elementwise) ----------------
__global__ __launch_bounds__(256) void split_kernel(const float4* __restrict__ x,
                                                    __nv_bfloat16* __restrict__ hi,
                                                    __nv_bfloat16* __restrict__ lo, int n4) {
    int i = blockIdx.x * 256 + threadIdx.x;
    if (i >= n4) return;
    float4 v = x[i];
    float vs[4] = {v.x, v.y, v.z, v.w};
    __nv_bfloat16 h[4], l[4];
#pragma unroll
    for (int j = 0; j < 4; j++) {
        h[j] = __float2bfloat16(vs[j]);
        l[j] = __float2bfloat16(vs[j] - __bfloat162float(h[j]));
    }
    __nv_bfloat162* hp = reinterpret_cast<__nv_bfloat162*>(hi) + 2 * (size_t)i;
    __nv_bfloat162* lp = reinterpret_cast<__nv_bfloat162*>(lo) + 2 * (size_t)i;
    hp[0] = __halves2bfloat162(h[0], h[1]);
    hp[1] = __halves2bfloat162(h[2], h[3]);
    lp[0] = __halves2bfloat162(l[0], l[1]);
    lp[1] = __halves2bfloat162(l[2], l[3]);
}

// ---------------- transpose + bf16 split: W[K][N] -> Wt_hi/lo[N][K] ----------------
__global__ __launch_bounds__(256) void tsplit_kernel(const float* __restrict__ W,
                                                     __nv_bfloat16* __restrict__ hi,
                                                     __nv_bfloat16* __restrict__ lo,
                                                     int K, int N) {
    __shared__ float t[32][33];
    int n0 = blockIdx.x * 32, k0 = blockIdx.y * 32;
    int tx = threadIdx.x & 31, ty = threadIdx.x >> 5;
#pragma unroll
    for (int i = 0; i < 4; i++)
        t[ty + i * 8][tx] = W[(size_t)(k0 + ty + i * 8) * N + n0 + tx];
    __syncthreads();
#pragma unroll
    for (int i = 0; i < 4; i++) {
        int n = n0 + ty + i * 8, k = k0 + tx;
        float v = t[tx][ty + i * 8];
        __nv_bfloat16 h = __float2bfloat16(v);
        hi[(size_t)n * K + k] = h;
        lo[(size_t)n * K + k] = __float2bfloat16(v - __bfloat162float(h));
    }
}

// ---------------- HMMA bf16-split GEMM (unchanged from R6) ----------------
#define GBM 128
#define GBN 128
#define GBK 32
#define SROW 80
#define SA_HI 0
#define SA_LO 10240
#define SB_HI 20480
#define SB_LO 30720
#define STAGE 40960
#define GEMM_SMEM (2 * STAGE)

__global__ __launch_bounds__(256, 1) void gemm_kernel(
    const __nv_bfloat16* __restrict__ Ahi, const __nv_bfloat16* __restrict__ Alo,
    const __nv_bfloat16* __restrict__ Bhi, const __nv_bfloat16* __restrict__ Blo,
    float* __restrict__ C, int M, int N, int Kd) {
    extern __shared__ char smem[];
    const uint32_t sb = smem_u32(smem);
    const int tid = threadIdx.x, lane = tid & 31, wid = tid >> 5;
    const int m0 = blockIdx.y * GBM, n0 = blockIdx.x * GBN;

    const int wm = (wid & 1) * 64;
    const int wn = (wid >> 1) * 32;

    const uint32_t a_ro = (uint32_t)(wm + (lane & 15)) * SROW + ((lane >> 4) * 16);
    const uint32_t b_ro = (uint32_t)(wn + ((lane >> 4) << 3) + (lane & 7)) * SROW + (((lane >> 3) & 1) * 16);

    float acc[4][4][4];
#pragma unroll
    for (int a = 0; a < 4; a++)
#pragma unroll
        for (int b = 0; b < 4; b++)
#pragma unroll
            for (int c = 0; c < 4; c++) acc[a][b][c] = 0.0f;

    const int NC = Kd / GBK;

    auto stage_load = [&](int c, int st) {
        uint32_t s0 = sb + st * STAGE;
        int k0 = c * GBK;
#pragma unroll
        for (int i = 0; i < 2; i++) {
            int idx = tid + i * 256;
            int r = idx >> 2, seg = idx & 3;
            uint32_t so = (uint32_t)(r * SROW + seg * 16);
            const char* ga = (const char*)(Ahi + (size_t)(m0 + r) * Kd + k0) + seg * 16;
            const char* gal = (const char*)(Alo + (size_t)(m0 + r) * Kd + k0) + seg * 16;
            const char* gb = (const char*)(Bhi + (size_t)(n0 + r) * Kd + k0) + seg * 16;
            const char* gbl = (const char*)(Blo + (size_t)(n0 + r) * Kd + k0) + seg * 16;
            cp16(s0 + SA_HI + so, ga);
            cp16(s0 + SA_LO + so, gal);
            cp16(s0 + SB_HI + so, gb);
            cp16(s0 + SB_LO + so, gbl);
        }
        asm volatile("cp.async.commit_group;" ::: "memory");
    };

    stage_load(0, 0);

    for (int c = 0; c < NC; ++c) {
        if (c + 1 < NC) {
            stage_load(c + 1, (c + 1) & 1);
            asm volatile("cp.async.wait_group 1;" ::: "memory");
        } else {
            asm volatile("cp.async.wait_group 0;" ::: "memory");
        }
        __syncthreads();

        const uint32_t s0 = sb + (c & 1) * STAGE;
#pragma unroll
        for (int ks = 0; ks < 2; ks++) {
            uint32_t ah[4][4], al[4][4], bh[2][4], bl[2][4];
#pragma unroll
            for (int mf = 0; mf < 4; mf++) {
                uint32_t ao = a_ro + (uint32_t)(mf * 16) * SROW + ks * 32;
                LDSM4(ah[mf], s0 + SA_HI + ao);
                LDSM4(al[mf], s0 + SA_LO + ao);
            }
#pragma unroll
            for (int p = 0; p < 2; p++) {
                uint32_t bo = b_ro + (uint32_t)(p * 16) * SROW + ks * 32;
                LDSM4(bh[p], s0 + SB_HI + bo);
                LDSM4(bl[p], s0 + SB_LO + bo);
            }
#pragma unroll
            for (int mf = 0; mf < 4; mf++)
#pragma unroll
                for (int nf = 0; nf < 4; nf++) {
                    uint32_t h0 = bh[nf >> 1][(nf & 1) * 2], h1 = bh[nf >> 1][(nf & 1) * 2 + 1];
                    uint32_t l0 = bl[nf >> 1][(nf & 1) * 2], l1 = bl[nf >> 1][(nf & 1) * 2 + 1];
                    MMA16816(acc[mf][nf], ah[mf], h0, h1);
                    MMA16816(acc[mf][nf], ah[mf], l0, l1);
                    MMA16816(acc[mf][nf], al[mf], h0, h1);
                }
        }
        __syncthreads();
    }

    const int gid = lane >> 2, tig = lane & 3;
#pragma unroll
    for (int mf = 0; mf < 4; mf++)
#pragma unroll
        for (int nf = 0; nf < 4; nf++) {
            int row = m0 + wm + mf * 16 + gid;
            int col = n0 + wn + nf * 8 + tig * 2;
            float* cp0 = C + (size_t)row * N + col;
            float* cp1 = C + (size_t)(row + 8) * N + col;
            *(float2*)cp0 = make_float2(acc[mf][nf][0], acc[mf][nf][1]);
            *(float2*)cp1 = make_float2(acc[mf][nf][2], acc[mf][nf][3]);
        }
}

// ---------------- fused per-head RMSNorm + RoPE -> bf16 hi/lo Q,K ----------------
__global__ __launch_bounds__(128) void rmsnorm_rope_kernel(const float* __restrict__ q_w,
                                                           const float* __restrict__ k_w) {
    const int t = blockIdx.x;
    const int hy = blockIdx.y;
    const int i = threadIdx.x;

    const float* base;
    const float* w;
    __nv_bfloat16 *oh, *ol;
    size_t off;
    if (hy < NH) {
        off = (size_t)t * NQ + hy * HD;
        base = g_Q + off; w = q_w; oh = g_Qhi + off; ol = g_Qlo + off;
    } else {
        off = (size_t)t * NKVD + (hy - NH) * HD;
        base = g_K + off; w = k_w; oh = g_Khi + off; ol = g_Klo + off;
    }

    float x = base[i];
    float v = x * x;
#pragma unroll
    for (int o = 16; o > 0; o >>= 1) v += __shfl_xor_sync(0xffffffffu, v, o);
    __shared__ float ws[4];
    const int lane = i & 31, wid = i >> 5;
    if (lane == 0) ws[wid] = v;
    __syncthreads();
    float sum = ws[0] + ws[1] + ws[2] + ws[3];

    float r = rsqrtf(sum * (1.0f / HD) + 1e-6f);
    float xn = w[i] * (x * r);

    __shared__ float sh[HD];
    sh[i] = xn;
    __syncthreads();

    const int j = i & 63;
    float inv_freq = 1.0f / powf(1000000.0f, (float)j * (1.0f / 64.0f));
    float ang = (float)t * inv_freq;
    float c = cosf(ang), s = sinf(ang);
    float rot = (i < 64) ? -sh[i + 64] : sh[i - 64];
    float y = xn * c + rot * s;

    __nv_bfloat16 hb = __float2bfloat16(y);
    oh[i] = hb;
    ol[i] = __float2bfloat16(y - __bfloat162float(hb));
}

// ---------------- HMMA causal flash attention ----------------
// BM=64 q rows/CTA, BN=64 kv per tile, 4 warps (each m16 x full n64).
// S = Qh*Kh + Ql*Kh + Qh*Kl (3-pass); PV = Ph*Vh + Pl*Vh + Ph*Vl (3-pass),
// P fragments repacked reg->reg (C-frag layout == A-frag layout).
#define A_SROW 272      // 128 bf16 = 256B + 16B pad
#define AQH 0
#define AQL 17408
#define AKH 34816
#define AKL 52224
#define AVH 69632
#define AVL 87040
#define ATTN_SMEM 104448

__global__ __launch_bounds__(128, 2) void attn_kernel(
    const __nv_bfloat16* __restrict__ Qh, const __nv_bfloat16* __restrict__ Ql,
    const __nv_bfloat16* __restrict__ Kh, const __nv_bfloat16* __restrict__ Kl,
    const __nv_bfloat16* __restrict__ Vh, const __nv_bfloat16* __restrict__ Vl,
    __nv_bfloat16* __restrict__ Ohi, __nv_bfloat16* __restrict__ Olo) {
    extern __shared__ char smc[];
    const uint32_t sb = smem_u32(smc);
    const int tid = threadIdx.x, lane = tid & 31, wid = tid >> 5;
    const int qtile = blockIdx.x, h = blockIdx.y;
    const int q0 = qtile * 64, kvh = h >> 2;
    const int gid = lane >> 2, tig = lane & 3, wm = wid * 16;

    const uint32_t a_ro = (uint32_t)(wm + (lane & 15)) * A_SROW + ((lane >> 4) * 16);
    const uint32_t b_ro = (uint32_t)(((lane >> 4) << 3) + (lane & 7)) * A_SROW + (((lane >> 3) & 1) * 16);
    const uint32_t v_ro = (uint32_t)((((lane >> 3) & 1) * 8) + (lane & 7)) * A_SROW + ((lane >> 4) * 16);

    // Q tile load (once)
#pragma unroll
    for (int i = 0; i < 8; i++) {
        int idx = tid + i * 128;
        int r = idx >> 4, sg = idx & 15;
        uint32_t so = (uint32_t)(r * A_SROW + sg * 16);
        size_t go = (size_t)(q0 + r) * NQ + h * HD + sg * 8;
        cp16(sb + AQH + so, Qh + go);
        cp16(sb + AQL + so, Ql + go);
    }
    asm volatile("cp.async.commit_group;" ::: "memory");

    float o[16][4];
#pragma unroll
    for (int a = 0; a < 16; a++)
#pragma unroll
        for (int b = 0; b < 4; b++) o[a][b] = 0.0f;
    float m_i[2] = {-1e30f, -1e30f}, l_i[2] = {0.0f, 0.0f};
    const float scale = 0.08838834764831845f;

    const int ntiles = qtile + 1;
    for (int kt = 0; kt < ntiles; kt++) {
        const int k0 = kt * 64;
        __syncthreads();
#pragma unroll
        for (int i = 0; i < 8; i++) {
            int idx = tid + i * 128;
            int r = idx >> 4, sg = idx & 15;
            uint32_t so = (uint32_t)(r * A_SROW + sg * 16);
            size_t go = (size_t)(k0 + r) * NKVD + kvh * HD + sg * 8;
            cp16(sb + AKH + so, Kh + go);
            cp16(sb + AKL + so, Kl + go);
            cp16(sb + AVH + so, Vh + go);
            cp16(sb + AVL + so, Vl + go);
        }
        asm volatile("cp.async.commit_group;" ::: "memory");
        asm volatile("cp.async.wait_group 0;" ::: "memory");
        __syncthreads();

        // ---- S = Q K^T (3-pass split) ----
        float s[8][4];
#pragma unroll
        for (int nf = 0; nf < 8; nf++)
#pragma unroll
            for (int e = 0; e < 4; e++) s[nf][e] = 0.0f;

#pragma unroll
        for (int ks = 0; ks < 8; ks++) {
            uint32_t ah[4], al[4], bh[4][4], bl[4][4];
            uint32_t ao = a_ro + ks * 32;
            LDSM4(ah, sb + AQH + ao);
            LDSM4(al, sb + AQL + ao);
#pragma unroll
            for (int p = 0; p < 4; p++) {
                uint32_t bo = b_ro + (uint32_t)(p * 16) * A_SROW + ks * 32;
                LDSM4(bh[p], sb + AKH + bo);
                LDSM4(bl[p], sb + AKL + bo);
            }
#pragma unroll
            for (int nf = 0; nf < 8; nf++) {
                uint32_t h0 = bh[nf >> 1][(nf & 1) * 2], h1 = bh[nf >> 1][(nf & 1) * 2 + 1];
                uint32_t l0 = bl[nf >> 1][(nf & 1) * 2], l1 = bl[nf >> 1][(nf & 1) * 2 + 1];
                MMA16816(s[nf], ah, h0, h1);
                MMA16816(s[nf], al, h0, h1);
                MMA16816(s[nf], ah, l0, l1);
            }
        }

        // ---- scale + causal mask ----
        const bool diag = (kt == qtile);
#pragma unroll
        for (int nf = 0; nf < 8; nf++)
#pragma unroll
            for (int e = 0; e < 4; e++) {
                float v = s[nf][e] * scale;
                if (diag) {
                    int row = wm + gid + ((e >> 1) << 3);
                    int col = nf * 8 + tig * 2 + (e & 1);
                    if (col > row) v = -1e30f;
                }
                s[nf][e] = v;
            }

        // ---- online softmax ----
        float fac[2];
#pragma unroll
        for (int r = 0; r < 2; r++) {
            float mx = -1e30f;
#pragma unroll
            for (int nf = 0; nf < 8; nf++)
                mx = fmaxf(mx, fmaxf(s[nf][r * 2], s[nf][r * 2 + 1]));
            mx = fmaxf(mx, __shfl_xor_sync(0xffffffffu, mx, 1));
            mx = fmaxf(mx, __shfl_xor_sync(0xffffffffu, mx, 2));
            float mn = fmaxf(m_i[r], mx);
            fac[r] = __expf(m_i[r] - mn);
            m_i[r] = mn;
            l_i[r] *= fac[r];
        }
#pragma unroll
        for (int nf = 0; nf < 16; nf++) {
            o[nf][0] *= fac[0]; o[nf][1] *= fac[0];
            o[nf][2] *= fac[1]; o[nf][3] *= fac[1];
        }
        float rs[2] = {0.0f, 0.0f};
#pragma unroll
        for (int nf = 0; nf < 8; nf++)
#pragma unroll
            for (int e = 0; e < 4; e++) {
                float p = __expf(s[nf][e] - m_i[e >> 1]);
                s[nf][e] = p;
                rs[e >> 1] += p;
            }
#pragma unroll
        for (int r = 0; r < 2; r++) {
            rs[r] += __shfl_xor_sync(0xffffffffu, rs[r], 1);
            rs[r] += __shfl_xor_sync(0xffffffffu, rs[r], 2);
            l_i[r] += rs[r];
        }

        // ---- repack P (C-frag -> A-frag, hi/lo) ----
        uint32_t ph[4][4], pl[4][4];
#pragma unroll
        for (int kf = 0; kf < 4; kf++) {
            float* f0 = s[2 * kf];
            float* f1 = s[2 * kf + 1];
            float v0[8] = {f0[0], f0[1], f0[2], f0[3], f1[0], f1[1], f1[2], f1[3]};
            float r0[8];
#pragma unroll
            for (int q = 0; q < 8; q++) {
                __nv_bfloat16 hb = __float2bfloat16(v0[q]);
                r0[q] = v0[q] - __bfloat162float(hb);
            }
            ph[kf][0] = pack_bf2(v0[0], v0[1]);
            ph[kf][1] = pack_bf2(v0[2], v0[3]);
            ph[kf][2] = pack_bf2(v0[4], v0[5]);
            ph[kf][3] = pack_bf2(v0[6], v0[7]);
            pl[kf][0] = pack_bf2(r0[0], r0[1]);
            pl[kf][1] = pack_bf2(r0[2], r0[3]);
            pl[kf][2] = pack_bf2(r0[4], r0[5]);
            pl[kf][3] = pack_bf2(r0[6], r0[7]);
        }

        // ---- O += P V (3-pass split, V via ldmatrix.trans) ----
#pragma unroll
        for (int kf = 0; kf < 4; kf++) {
#pragma unroll
            for (int j = 0; j < 8; j++) {
                uint32_t vh4[4], vl4[4];
                uint32_t vo = v_ro + (uint32_t)(kf * 16) * A_SROW + j * 32;
                LDSM4T(vh4, sb + AVH + vo);
                LDSM4T(vl4, sb + AVL + vo);
                MMA16816(o[2 * j], ph[kf], vh4[0], vh4[1]);
                MMA16816(o[2 * j], pl[kf], vh4[0], vh4[1]);
                MMA16816(o[2 * j], ph[kf], vl4[0], vl4[1]);
                MMA16816(o[2 * j + 1], ph[kf], vh4[2], vh4[3]);
                MMA16816(o[2 * j + 1], pl[kf], vh4[2], vh4[3]);
                MMA16816(o[2 * j + 1], ph[kf], vl4[2], vl4[3]);
            }
        }
    }

    // ---- epilogue: normalize, split to bf16 hi/lo, store ----
    float inv[2] = {1.0f / l_i[0], 1.0f / l_i[1]};
    int row0 = q0 + wm + gid;
#pragma unroll
    for (int nf = 0; nf < 16; nf++) {
        int col = h * HD + nf * 8 + tig * 2;
#pragma unroll
        for (int r = 0; r < 2; r++) {
            float o0 = o[nf][r * 2] * inv[r];
            float o1 = o[nf][r * 2 + 1] * inv[r];
            __nv_bfloat16 h0 = __float2bfloat16(o0), h1 = __float2bfloat16(o1);
            float l0 = o0 - __bfloat162float(h0), l1 = o1 - __bfloat162float(h1);
            size_t base = (size_t)(row0 + r * 8) * NQ + col;
            *(__nv_bfloat162*)(Ohi + base) = __halves2bfloat162(h0, h1);
            *(__nv_bfloat162*)(Olo + base) = __halves2bfloat162(__float2bfloat16(l0), __float2bfloat16(l1));
        }
    }
}

// ---------------- launcher ----------------
extern "C" void kernel_launch(void* const* d_in, const int* in_sizes, int n_in,
                              void* d_out, int out_size) {
    const float* x  = (const float*)d_in[0];
    const float* Wq = (const float*)d_in[1];
    const float* Wk = (const float*)d_in[2];
    const float* Wv = (const float*)d_in[3];
    const float* Wo = (const float*)d_in[4];
    const float* qw = (const float*)d_in[5];
    const float* kw = (const float*)d_in[6];
    float* out = (float*)d_out;

    float *Qb, *Kb, *Vb;
    cudaGetSymbolAddress((void**)&Qb, g_Q);
    cudaGetSymbolAddress((void**)&Kb, g_K);
    cudaGetSymbolAddress((void**)&Vb, g_V);
    __nv_bfloat16 *Xhi, *Xlo, *Ohi, *Olo, *Qhi, *Qlo, *Khi, *Klo, *Vhi, *Vlo;
    __nv_bfloat16 *Wqh, *Wql, *Wkh, *Wkl, *Wvh, *Wvl, *Woh, *Wol;
    cudaGetSymbolAddress((void**)&Xhi, g_Xhi);
    cudaGetSymbolAddress((void**)&Xlo, g_Xlo);
    cudaGetSymbolAddress((void**)&Ohi, g_Ohi);
    cudaGetSymbolAddress((void**)&Olo, g_Olo);
    cudaGetSymbolAddress((void**)&Qhi, g_Qhi);
    cudaGetSymbolAddress((void**)&Qlo, g_Qlo);
    cudaGetSymbolAddress((void**)&Khi, g_Khi);
    cudaGetSymbolAddress((void**)&Klo, g_Klo);
    cudaGetSymbolAddress((void**)&Vhi, g_Vhi);
    cudaGetSymbolAddress((void**)&Vlo, g_Vlo);
    cudaGetSymbolAddress((void**)&Wqh, g_Wqt_hi);
    cudaGetSymbolAddress((void**)&Wql, g_Wqt_lo);
    cudaGetSymbolAddress((void**)&Wkh, g_Wkt_hi);
    cudaGetSymbolAddress((void**)&Wkl, g_Wkt_lo);
    cudaGetSymbolAddress((void**)&Wvh, g_Wvt_hi);
    cudaGetSymbolAddress((void**)&Wvl, g_Wvt_lo);
    cudaGetSymbolAddress((void**)&Woh, g_Wot_hi);
    cudaGetSymbolAddress((void**)&Wol, g_Wot_lo);

    cudaFuncSetAttribute(gemm_kernel, cudaFuncAttributeMaxDynamicSharedMemorySize, GEMM_SMEM);
    cudaFuncSetAttribute(attn_kernel, cudaFuncAttributeMaxDynamicSharedMemorySize, ATTN_SMEM);

    // 1. bf16 splits of X and transposed weights
    int n4x = T_SEQ * D_MODEL / 4;
    split_kernel<<<(n4x + 255) / 256, 256>>>((const float4*)x, Xhi, Xlo, n4x);
    tsplit_kernel<<<dim3(NQ / 32, D_MODEL / 32), 256>>>(Wq, Wqh, Wql, D_MODEL, NQ);
    tsplit_kernel<<<dim3(NKVD / 32, D_MODEL / 32), 256>>>(Wk, Wkh, Wkl, D_MODEL, NKVD);
    tsplit_kernel<<<dim3(NKVD / 32, D_MODEL / 32), 256>>>(Wv, Wvh, Wvl, D_MODEL, NKVD);
    tsplit_kernel<<<dim3(NQ / 32, D_MODEL / 32), 256>>>(Wo, Woh, Wol, NQ, D_MODEL);

    // 2. QKV projections (HMMA bf16-split)
    gemm_kernel<<<dim3(NQ / GBN, T_SEQ / GBM), 256, GEMM_SMEM>>>(Xhi, Xlo, Wqh, Wql, Qb, T_SEQ, NQ, D_MODEL);
    gemm_kernel<<<dim3(NKVD / GBN, T_SEQ / GBM), 256, GEMM_SMEM>>>(Xhi, Xlo, Wkh, Wkl, Kb, T_SEQ, NKVD, D_MODEL);
    gemm_kernel<<<dim3(NKVD / GBN, T_SEQ / GBM), 256, GEMM_SMEM>>>(Xhi, Xlo, Wvh, Wvl, Vb, T_SEQ, NKVD, D_MODEL);

    // 3. RMSNorm + RoPE -> bf16 hi/lo Q,K ; V -> bf16 hi/lo
    rmsnorm_rope_kernel<<<dim3(T_SEQ, NH + NKV), 128>>>(qw, kw);
    int n4v = T_SEQ * NKVD / 4;
    split_kernel<<<(n4v + 255) / 256, 256>>>((const float4*)Vb, Vhi, Vlo, n4v);

    // 4. HMMA causal flash attention -> bf16 hi/lo O
    attn_kernel<<<dim3(T_SEQ / 64, NH), 128, ATTN_SMEM>>>(Qhi, Qlo, Khi, Klo, Vhi, Vlo, Ohi, Olo);

    // 5. output projection (HMMA bf16-split)
    gemm_kernel<<<dim3(D_MODEL / GBN, T_SEQ / GBM), 256, GEMM_SMEM>>>(Ohi, Olo, Woh, Wol, out, T_SEQ, D_MODEL, NQ);
}

// round 8
// speedup vs baseline: 4.8693x; 1.4806x over previous
#include <cuda_runtime.h>
#include <cuda_bf16.h>
#include <cuda_fp16.h>
#include <math.h>
#include <math_constants.h>
#include <stdint.h>

#define T_SEQ   2048
#define D_MODEL 4096
#define NH      32
#define NKV     8
#define HD      128
#define NQ      (NH * HD)    // 4096
#define NKVD    (NKV * HD)   // 1024
#define NQKV    (NQ + 2 * NKVD)  // 6144

// ---------------- scratch (device globals; no allocations allowed) ----------------
__device__ float g_Q[T_SEQ * NQ];
__device__ float g_K[T_SEQ * NKVD];
__device__ float g_V[T_SEQ * NKVD];

__device__ __half g_Xhi[T_SEQ * D_MODEL];
__device__ __half g_Xlo[T_SEQ * D_MODEL];
__device__ __half g_Ohi[T_SEQ * NQ];
__device__ __half g_Olo[T_SEQ * NQ];
__device__ __half g_Wqkv[NQKV * D_MODEL];   // [6144][4096] fp16, rows: Wq^T, Wk^T, Wv^T
__device__ __half g_Wot[D_MODEL * NQ];      // Wo^T fp16

__device__ __nv_bfloat16 g_Qhi[T_SEQ * NQ];
__device__ __nv_bfloat16 g_Qlo[T_SEQ * NQ];
__device__ __nv_bfloat16 g_Khi[T_SEQ * NKVD];
__device__ __nv_bfloat16 g_Klo[T_SEQ * NKVD];
__device__ __nv_bfloat16 g_Vhi[T_SEQ * NKVD];
__device__ __nv_bfloat16 g_Vlo[T_SEQ * NKVD];

// ---------------- helpers ----------------
static __device__ __forceinline__ uint32_t smem_u32(const void* p) {
    uint32_t a;
    asm("{ .reg .u64 t; cvta.to.shared.u64 t, %1; cvt.u32.u64 %0, t; }" : "=r"(a) : "l"(p));
    return a;
}
static __device__ __forceinline__ void cp16(uint32_t s, const void* g) {
    asm volatile("cp.async.cg.shared.global [%0], [%1], 16;" :: "r"(s), "l"(g));
}
static __device__ __forceinline__ uint32_t pack_bf2(float a, float b) {
    __nv_bfloat162 t = __halves2bfloat162(__float2bfloat16(a), __float2bfloat16(b));
    return *(uint32_t*)&t;
}

#define LDSM4(R, ADDR)                                                              \
    asm volatile("ldmatrix.sync.aligned.m8n8.x4.shared.b16 {%0,%1,%2,%3}, [%4];"    \
                 : "=r"((R)[0]), "=r"((R)[1]), "=r"((R)[2]), "=r"((R)[3])           \
                 : "r"(ADDR))

#define LDSM4T(R, ADDR)                                                             \
    asm volatile("ldmatrix.sync.aligned.m8n8.x4.trans.shared.b16 {%0,%1,%2,%3}, [%4];" \
                 : "=r"((R)[0]), "=r"((R)[1]), "=r"((R)[2]), "=r"((R)[3])           \
                 : "r"(ADDR))

// bf16 MMA (attention)
#define MMA16816(C, A, B0, B1)                                                      \
    asm volatile("mma.sync.aligned.m16n8k16.row.col.f32.bf16.bf16.f32 "             \
                 "{%0,%1,%2,%3}, {%4,%5,%6,%7}, {%8,%9}, {%0,%1,%2,%3};"            \
                 : "+f"((C)[0]), "+f"((C)[1]), "+f"((C)[2]), "+f"((C)[3])           \
                 : "r"((A)[0]), "r"((A)[1]), "r"((A)[2]), "r"((A)[3]),              \
                   "r"(B0), "r"(B1))

// fp16 MMA (projections)
#define MMAH16816(C, A, B0, B1)                                                     \
    asm volatile("mma.sync.aligned.m16n8k16.row.col.f32.f16.f16.f32 "               \
                 "{%0,%1,%2,%3}, {%4,%5,%6,%7}, {%8,%9}, {%0,%1,%2,%3};"            \
                 : "+f"((C)[0]), "+f"((C)[1]), "+f"((C)[2]), "+f"((C)[3])           \
                 : "r"((A)[0]), "r"((A)[1]), "r"((A)[2]), "r"((A)[3]),              \
                   "r"(B0), "r"(B1))

// ---------------- fp16 hi/lo split (elementwise) ----------------
__global__ __launch_bounds__(256) void splith_kernel(const float4* __restrict__ x,
                                                     __half* __restrict__ hi,
                                                     __half* __restrict__ lo, int n4) {
    int i = blockIdx.x * 256 + threadIdx.x;
    if (i >= n4) return;
    float4 v = x[i];
    float vs[4] = {v.x, v.y, v.z, v.w};
    __half h[4], l[4];
#pragma unroll
    for (int j = 0; j < 4; j++) {
        h[j] = __float2half(vs[j]);
        l[j] = __float2half(vs[j] - __half2float(h[j]));
    }
    __half2* hp = reinterpret_cast<__half2*>(hi) + 2 * (size_t)i;
    __half2* lp = reinterpret_cast<__half2*>(lo) + 2 * (size_t)i;
    hp[0] = __halves2half2(h[0], h[1]);
    hp[1] = __halves2half2(h[2], h[3]);
    lp[0] = __halves2half2(l[0], l[1]);
    lp[1] = __halves2half2(l[2], l[3]);
}

// ---------------- bf16 hi/lo split (for V, attention operand) ----------------
__global__ __launch_bounds__(256) void split_kernel(const float4* __restrict__ x,
                                                    __nv_bfloat16* __restrict__ hi,
                                                    __nv_bfloat16* __restrict__ lo, int n4) {
    int i = blockIdx.x * 256 + threadIdx.x;
    if (i >= n4) return;
    float4 v = x[i];
    float vs[4] = {v.x, v.y, v.z, v.w};
    __nv_bfloat16 h[4], l[4];
#pragma unroll
    for (int j = 0; j < 4; j++) {
        h[j] = __float2bfloat16(vs[j]);
        l[j] = __float2bfloat16(vs[j] - __bfloat162float(h[j]));
    }
    __nv_bfloat162* hp = reinterpret_cast<__nv_bfloat162*>(hi) + 2 * (size_t)i;
    __nv_bfloat162* lp = reinterpret_cast<__nv_bfloat162*>(lo) + 2 * (size_t)i;
    hp[0] = __halves2bfloat162(h[0], h[1]);
    hp[1] = __halves2bfloat162(h[2], h[3]);
    lp[0] = __halves2bfloat162(l[0], l[1]);
    lp[1] = __halves2bfloat162(l[2], l[3]);
}

// ---------------- transpose to fp16: W[4096][N] -> dst[(row_off+n)][4096] ----------------
__global__ __launch_bounds__(256) void tf16_kernel(const float* __restrict__ W,
                                                   __half* __restrict__ dst,
                                                   int N, int row_off) {
    __shared__ float t[32][33];
    int n0 = blockIdx.x * 32, k0 = blockIdx.y * 32;
    int tx = threadIdx.x & 31, ty = threadIdx.x >> 5;
#pragma unroll
    for (int i = 0; i < 4; i++)
        t[ty + i * 8][tx] = W[(size_t)(k0 + ty + i * 8) * N + n0 + tx];
    __syncthreads();
#pragma unroll
    for (int i = 0; i < 4; i++) {
        int n = n0 + ty + i * 8, k = k0 + tx;
        dst[(size_t)(row_off + n) * D_MODEL + k] = __float2half(t[tx][ty + i * 8]);
    }
}

// ---------------- fp16 2-pass GEMM ----------------
// C = (Ahi+Alo)[M,4096] @ B[N,4096]^T. A hi/lo fp16, B single fp16, C fp32.
// CTA 128x128x32, 8 warps; acc += Ah*B + Al*B.
#define GBM 128
#define GBN 128
#define GBK 32
#define SROW 80
#define G2A_HI 0
#define G2A_LO 10240
#define G2B    20480
#define G2STAGE 30720
#define GEMM2_SMEM (2 * G2STAGE)

__global__ __launch_bounds__(256, 2) void gemm2_kernel(
    const __half* __restrict__ Ahi, const __half* __restrict__ Alo,
    const __half* __restrict__ B,
    float* __restrict__ Cq, float* __restrict__ Ck, float* __restrict__ Cv,
    int Kd, int qkv_mode) {
    extern __shared__ char smem[];
    const uint32_t sb = smem_u32(smem);
    const int tid = threadIdx.x, lane = tid & 31, wid = tid >> 5;
    const int m0 = blockIdx.y * GBM, n0 = blockIdx.x * GBN;

    const int wm = (wid & 1) * 64;
    const int wn = (wid >> 1) * 32;

    const uint32_t a_ro = (uint32_t)(wm + (lane & 15)) * SROW + ((lane >> 4) * 16);
    const uint32_t b_ro = (uint32_t)(wn + ((lane >> 4) << 3) + (lane & 7)) * SROW + (((lane >> 3) & 1) * 16);

    float acc[4][4][4];
#pragma unroll
    for (int a = 0; a < 4; a++)
#pragma unroll
        for (int b = 0; b < 4; b++)
#pragma unroll
            for (int c = 0; c < 4; c++) acc[a][b][c] = 0.0f;

    const int NC = Kd / GBK;

    auto stage_load = [&](int c, int st) {
        uint32_t s0 = sb + st * G2STAGE;
        int k0 = c * GBK;
#pragma unroll
        for (int i = 0; i < 2; i++) {
            int idx = tid + i * 256;          // 0..511
            int r = idx >> 2, seg = idx & 3;
            uint32_t so = (uint32_t)(r * SROW + seg * 16);
            cp16(s0 + G2A_HI + so, Ahi + (size_t)(m0 + r) * Kd + k0 + seg * 8);
            cp16(s0 + G2A_LO + so, Alo + (size_t)(m0 + r) * Kd + k0 + seg * 8);
            cp16(s0 + G2B + so, B + (size_t)(n0 + r) * Kd + k0 + seg * 8);
        }
        asm volatile("cp.async.commit_group;" ::: "memory");
    };

    stage_load(0, 0);

    for (int c = 0; c < NC; ++c) {
        if (c + 1 < NC) {
            stage_load(c + 1, (c + 1) & 1);
            asm volatile("cp.async.wait_group 1;" ::: "memory");
        } else {
            asm volatile("cp.async.wait_group 0;" ::: "memory");
        }
        __syncthreads();

        const uint32_t s0 = sb + (c & 1) * G2STAGE;
#pragma unroll
        for (int ks = 0; ks < 2; ks++) {
            uint32_t ah[4][4], al[4][4], bh[2][4];
#pragma unroll
            for (int mf = 0; mf < 4; mf++) {
                uint32_t ao = a_ro + (uint32_t)(mf * 16) * SROW + ks * 32;
                LDSM4(ah[mf], s0 + G2A_HI + ao);
                LDSM4(al[mf], s0 + G2A_LO + ao);
            }
#pragma unroll
            for (int p = 0; p < 2; p++) {
                uint32_t bo = b_ro + (uint32_t)(p * 16) * SROW + ks * 32;
                LDSM4(bh[p], s0 + G2B + bo);
            }
#pragma unroll
            for (int mf = 0; mf < 4; mf++)
#pragma unroll
                for (int nf = 0; nf < 4; nf++) {
                    uint32_t b0 = bh[nf >> 1][(nf & 1) * 2], b1 = bh[nf >> 1][(nf & 1) * 2 + 1];
                    MMAH16816(acc[mf][nf], ah[mf], b0, b1);
                    MMAH16816(acc[mf][nf], al[mf], b0, b1);
                }
        }
        __syncthreads();
    }

    // epilogue with QKV routing (region boundaries are 128-aligned -> whole CTA in one region)
    float* Cp;
    int ldc, coff;
    if (qkv_mode && n0 >= NQ + NKVD)      { Cp = Cv; ldc = NKVD; coff = n0 - (NQ + NKVD); }
    else if (qkv_mode && n0 >= NQ)        { Cp = Ck; ldc = NKVD; coff = n0 - NQ; }
    else                                  { Cp = Cq; ldc = D_MODEL; coff = n0; }

    const int gid = lane >> 2, tig = lane & 3;
#pragma unroll
    for (int mf = 0; mf < 4; mf++)
#pragma unroll
        for (int nf = 0; nf < 4; nf++) {
            int row = m0 + wm + mf * 16 + gid;
            int col = coff + wn + nf * 8 + tig * 2;
            float* cp0 = Cp + (size_t)row * ldc + col;
            float* cp1 = Cp + (size_t)(row + 8) * ldc + col;
            *(float2*)cp0 = make_float2(acc[mf][nf][0], acc[mf][nf][1]);
            *(float2*)cp1 = make_float2(acc[mf][nf][2], acc[mf][nf][3]);
        }
}

// ---------------- fused per-head RMSNorm + RoPE -> bf16 hi/lo Q,K ----------------
__global__ __launch_bounds__(128) void rmsnorm_rope_kernel(const float* __restrict__ q_w,
                                                           const float* __restrict__ k_w) {
    const int t = blockIdx.x;
    const int hy = blockIdx.y;
    const int i = threadIdx.x;

    const float* base;
    const float* w;
    __nv_bfloat16 *oh, *ol;
    size_t off;
    if (hy < NH) {
        off = (size_t)t * NQ + hy * HD;
        base = g_Q + off; w = q_w; oh = g_Qhi + off; ol = g_Qlo + off;
    } else {
        off = (size_t)t * NKVD + (hy - NH) * HD;
        base = g_K + off; w = k_w; oh = g_Khi + off; ol = g_Klo + off;
    }

    float x = base[i];
    float v = x * x;
#pragma unroll
    for (int o = 16; o > 0; o >>= 1) v += __shfl_xor_sync(0xffffffffu, v, o);
    __shared__ float ws[4];
    const int lane = i & 31, wid = i >> 5;
    if (lane == 0) ws[wid] = v;
    __syncthreads();
    float sum = ws[0] + ws[1] + ws[2] + ws[3];

    float r = rsqrtf(sum * (1.0f / HD) + 1e-6f);
    float xn = w[i] * (x * r);

    __shared__ float sh[HD];
    sh[i] = xn;
    __syncthreads();

    const int j = i & 63;
    float inv_freq = 1.0f / powf(1000000.0f, (float)j * (1.0f / 64.0f));
    float ang = (float)t * inv_freq;
    float c = cosf(ang), s = sinf(ang);
    float rot = (i < 64) ? -sh[i + 64] : sh[i - 64];
    float y = xn * c + rot * s;

    __nv_bfloat16 hb = __float2bfloat16(y);
    oh[i] = hb;
    ol[i] = __float2bfloat16(y - __bfloat162float(hb));
}

// ---------------- HMMA causal flash attention (bf16 3-pass; fp16 hi/lo O out) ----------------
#define A_SROW 272
#define AQH 0
#define AQL 17408
#define AKH 34816
#define AKL 52224
#define AVH 69632
#define AVL 87040
#define ATTN_SMEM 104448

__global__ __launch_bounds__(128, 2) void attn_kernel(
    const __nv_bfloat16* __restrict__ Qh, const __nv_bfloat16* __restrict__ Ql,
    const __nv_bfloat16* __restrict__ Kh, const __nv_bfloat16* __restrict__ Kl,
    const __nv_bfloat16* __restrict__ Vh, const __nv_bfloat16* __restrict__ Vl,
    __half* __restrict__ Ohi, __half* __restrict__ Olo) {
    extern __shared__ char smc[];
    const uint32_t sb = smem_u32(smc);
    const int tid = threadIdx.x, lane = tid & 31, wid = tid >> 5;
    const int qtile = blockIdx.x, h = blockIdx.y;
    const int q0 = qtile * 64, kvh = h >> 2;
    const int gid = lane >> 2, tig = lane & 3, wm = wid * 16;

    const uint32_t a_ro = (uint32_t)(wm + (lane & 15)) * A_SROW + ((lane >> 4) * 16);
    const uint32_t b_ro = (uint32_t)(((lane >> 4) << 3) + (lane & 7)) * A_SROW + (((lane >> 3) & 1) * 16);
    const uint32_t v_ro = (uint32_t)((((lane >> 3) & 1) * 8) + (lane & 7)) * A_SROW + ((lane >> 4) * 16);

#pragma unroll
    for (int i = 0; i < 8; i++) {
        int idx = tid + i * 128;
        int r = idx >> 4, sg = idx & 15;
        uint32_t so = (uint32_t)(r * A_SROW + sg * 16);
        size_t go = (size_t)(q0 + r) * NQ + h * HD + sg * 8;
        cp16(sb + AQH + so, Qh + go);
        cp16(sb + AQL + so, Ql + go);
    }
    asm volatile("cp.async.commit_group;" ::: "memory");

    float o[16][4];
#pragma unroll
    for (int a = 0; a < 16; a++)
#pragma unroll
        for (int b = 0; b < 4; b++) o[a][b] = 0.0f;
    float m_i[2] = {-1e30f, -1e30f}, l_i[2] = {0.0f, 0.0f};
    const float scale = 0.08838834764831845f;

    const int ntiles = qtile + 1;
    for (int kt = 0; kt < ntiles; kt++) {
        const int k0 = kt * 64;
        __syncthreads();
#pragma unroll
        for (int i = 0; i < 8; i++) {
            int idx = tid + i * 128;
            int r = idx >> 4, sg = idx & 15;
            uint32_t so = (uint32_t)(r * A_SROW + sg * 16);
            size_t go = (size_t)(k0 + r) * NKVD + kvh * HD + sg * 8;
            cp16(sb + AKH + so, Kh + go);
            cp16(sb + AKL + so, Kl + go);
            cp16(sb + AVH + so, Vh + go);
            cp16(sb + AVL + so, Vl + go);
        }
        asm volatile("cp.async.commit_group;" ::: "memory");
        asm volatile("cp.async.wait_group 0;" ::: "memory");
        __syncthreads();

        float s[8][4];
#pragma unroll
        for (int nf = 0; nf < 8; nf++)
#pragma unroll
            for (int e = 0; e < 4; e++) s[nf][e] = 0.0f;

#pragma unroll
        for (int ks = 0; ks < 8; ks++) {
            uint32_t ah[4], al[4], bh[4][4], bl[4][4];
            uint32_t ao = a_ro + ks * 32;
            LDSM4(ah, sb + AQH + ao);
            LDSM4(al, sb + AQL + ao);
#pragma unroll
            for (int p = 0; p < 4; p++) {
                uint32_t bo = b_ro + (uint32_t)(p * 16) * A_SROW + ks * 32;
                LDSM4(bh[p], sb + AKH + bo);
                LDSM4(bl[p], sb + AKL + bo);
            }
#pragma unroll
            for (int nf = 0; nf < 8; nf++) {
                uint32_t h0 = bh[nf >> 1][(nf & 1) * 2], h1 = bh[nf >> 1][(nf & 1) * 2 + 1];
                uint32_t l0 = bl[nf >> 1][(nf & 1) * 2], l1 = bl[nf >> 1][(nf & 1) * 2 + 1];
                MMA16816(s[nf], ah, h0, h1);
                MMA16816(s[nf], al, h0, h1);
                MMA16816(s[nf], ah, l0, l1);
            }
        }

        const bool diag = (kt == qtile);
#pragma unroll
        for (int nf = 0; nf < 8; nf++)
#pragma unroll
            for (int e = 0; e < 4; e++) {
                float v = s[nf][e] * scale;
                if (diag) {
                    int row = wm + gid + ((e >> 1) << 3);
                    int col = nf * 8 + tig * 2 + (e & 1);
                    if (col > row) v = -1e30f;
                }
                s[nf][e] = v;
            }

        float fac[2];
#pragma unroll
        for (int r = 0; r < 2; r++) {
            float mx = -1e30f;
#pragma unroll
            for (int nf = 0; nf < 8; nf++)
                mx = fmaxf(mx, fmaxf(s[nf][r * 2], s[nf][r * 2 + 1]));
            mx = fmaxf(mx, __shfl_xor_sync(0xffffffffu, mx, 1));
            mx = fmaxf(mx, __shfl_xor_sync(0xffffffffu, mx, 2));
            float mn = fmaxf(m_i[r], mx);
            fac[r] = __expf(m_i[r] - mn);
            m_i[r] = mn;
            l_i[r] *= fac[r];
        }
#pragma unroll
        for (int nf = 0; nf < 16; nf++) {
            o[nf][0] *= fac[0]; o[nf][1] *= fac[0];
            o[nf][2] *= fac[1]; o[nf][3] *= fac[1];
        }
        float rs[2] = {0.0f, 0.0f};
#pragma unroll
        for (int nf = 0; nf < 8; nf++)
#pragma unroll
            for (int e = 0; e < 4; e++) {
                float p = __expf(s[nf][e] - m_i[e >> 1]);
                s[nf][e] = p;
                rs[e >> 1] += p;
            }
#pragma unroll
        for (int r = 0; r < 2; r++) {
            rs[r] += __shfl_xor_sync(0xffffffffu, rs[r], 1);
            rs[r] += __shfl_xor_sync(0xffffffffu, rs[r], 2);
            l_i[r] += rs[r];
        }

        uint32_t ph[4][4], pl[4][4];
#pragma unroll
        for (int kf = 0; kf < 4; kf++) {
            float* f0 = s[2 * kf];
            float* f1 = s[2 * kf + 1];
            float v0[8] = {f0[0], f0[1], f0[2], f0[3], f1[0], f1[1], f1[2], f1[3]};
            float r0[8];
#pragma unroll
            for (int q = 0; q < 8; q++) {
                __nv_bfloat16 hb = __float2bfloat16(v0[q]);
                r0[q] = v0[q] - __bfloat162float(hb);
            }
            ph[kf][0] = pack_bf2(v0[0], v0[1]);
            ph[kf][1] = pack_bf2(v0[2], v0[3]);
            ph[kf][2] = pack_bf2(v0[4], v0[5]);
            ph[kf][3] = pack_bf2(v0[6], v0[7]);
            pl[kf][0] = pack_bf2(r0[0], r0[1]);
            pl[kf][1] = pack_bf2(r0[2], r0[3]);
            pl[kf][2] = pack_bf2(r0[4], r0[5]);
            pl[kf][3] = pack_bf2(r0[6], r0[7]);
        }

#pragma unroll
        for (int kf = 0; kf < 4; kf++) {
#pragma unroll
            for (int j = 0; j < 8; j++) {
                uint32_t vh4[4], vl4[4];
                uint32_t vo = v_ro + (uint32_t)(kf * 16) * A_SROW + j * 32;
                LDSM4T(vh4, sb + AVH + vo);
                LDSM4T(vl4, sb + AVL + vo);
                MMA16816(o[2 * j], ph[kf], vh4[0], vh4[1]);
                MMA16816(o[2 * j], pl[kf], vh4[0], vh4[1]);
                MMA16816(o[2 * j], ph[kf], vl4[0], vl4[1]);
                MMA16816(o[2 * j + 1], ph[kf], vh4[2], vh4[3]);
                MMA16816(o[2 * j + 1], pl[kf], vh4[2], vh4[3]);
                MMA16816(o[2 * j + 1], ph[kf], vl4[2], vl4[3]);
            }
        }
    }

    // epilogue: normalize, split to fp16 hi/lo, store
    float inv[2] = {1.0f / l_i[0], 1.0f / l_i[1]};
    int row0 = q0 + wm + gid;
#pragma unroll
    for (int nf = 0; nf < 16; nf++) {
        int col = h * HD + nf * 8 + tig * 2;
#pragma unroll
        for (int r = 0; r < 2; r++) {
            float o0 = o[nf][r * 2] * inv[r];
            float o1 = o[nf][r * 2 + 1] * inv[r];
            __half h0 = __float2half(o0), h1 = __float2half(o1);
            float l0 = o0 - __half2float(h0), l1 = o1 - __half2float(h1);
            size_t base = (size_t)(row0 + r * 8) * NQ + col;
            *(__half2*)(Ohi + base) = __halves2half2(h0, h1);
            *(__half2*)(Olo + base) = __halves2half2(__float2half(l0), __float2half(l1));
        }
    }
}

// ---------------- launcher ----------------
extern "C" void kernel_launch(void* const* d_in, const int* in_sizes, int n_in,
                              void* d_out, int out_size) {
    const float* x  = (const float*)d_in[0];
    const float* Wq = (const float*)d_in[1];
    const float* Wk = (const float*)d_in[2];
    const float* Wv = (const float*)d_in[3];
    const float* Wo = (const float*)d_in[4];
    const float* qw = (const float*)d_in[5];
    const float* kw = (const float*)d_in[6];
    float* out = (float*)d_out;

    float *Qb, *Kb, *Vb;
    cudaGetSymbolAddress((void**)&Qb, g_Q);
    cudaGetSymbolAddress((void**)&Kb, g_K);
    cudaGetSymbolAddress((void**)&Vb, g_V);
    __half *Xhi, *Xlo, *Ohi, *Olo, *Wqkv, *Wot;
    cudaGetSymbolAddress((void**)&Xhi, g_Xhi);
    cudaGetSymbolAddress((void**)&Xlo, g_Xlo);
    cudaGetSymbolAddress((void**)&Ohi, g_Ohi);
    cudaGetSymbolAddress((void**)&Olo, g_Olo);
    cudaGetSymbolAddress((void**)&Wqkv, g_Wqkv);
    cudaGetSymbolAddress((void**)&Wot, g_Wot);
    __nv_bfloat16 *Qhi, *Qlo, *Khi, *Klo, *Vhi, *Vlo;
    cudaGetSymbolAddress((void**)&Qhi, g_Qhi);
    cudaGetSymbolAddress((void**)&Qlo, g_Qlo);
    cudaGetSymbolAddress((void**)&Khi, g_Khi);
    cudaGetSymbolAddress((void**)&Klo, g_Klo);
    cudaGetSymbolAddress((void**)&Vhi, g_Vhi);
    cudaGetSymbolAddress((void**)&Vlo, g_Vlo);

    cudaFuncSetAttribute(gemm2_kernel, cudaFuncAttributeMaxDynamicSharedMemorySize, GEMM2_SMEM);
    cudaFuncSetAttribute(attn_kernel, cudaFuncAttributeMaxDynamicSharedMemorySize, ATTN_SMEM);

    // 1. fp16 split of X; weights -> transposed fp16 (QKV merged)
    int n4x = T_SEQ * D_MODEL / 4;
    splith_kernel<<<(n4x + 255) / 256, 256>>>((const float4*)x, Xhi, Xlo, n4x);
    tf16_kernel<<<dim3(NQ / 32, D_MODEL / 32), 256>>>(Wq, Wqkv, NQ, 0);
    tf16_kernel<<<dim3(NKVD / 32, D_MODEL / 32), 256>>>(Wk, Wqkv, NKVD, NQ);
    tf16_kernel<<<dim3(NKVD / 32, D_MODEL / 32), 256>>>(Wv, Wqkv, NKVD, NQ + NKVD);
    tf16_kernel<<<dim3(NQ / 32, D_MODEL / 32), 256>>>(Wo, Wot, NQ, 0);

    // 2. merged QKV projection (fp16 2-pass)
    gemm2_kernel<<<dim3(NQKV / GBN, T_SEQ / GBM), 256, GEMM2_SMEM>>>(
        Xhi, Xlo, Wqkv, Qb, Kb, Vb, D_MODEL, 1);

    // 3. RMSNorm + RoPE -> bf16 hi/lo Q,K ; V -> bf16 hi/lo
    rmsnorm_rope_kernel<<<dim3(T_SEQ, NH + NKV), 128>>>(qw, kw);
    int n4v = T_SEQ * NKVD / 4;
    split_kernel<<<(n4v + 255) / 256, 256>>>((const float4*)Vb, Vhi, Vlo, n4v);

    // 4. HMMA causal flash attention -> fp16 hi/lo O
    attn_kernel<<<dim3(T_SEQ / 64, NH), 128, ATTN_SMEM>>>(Qhi, Qlo, Khi, Klo, Vhi, Vlo, Ohi, Olo);

    // 5. output projection (fp16 2-pass)
    gemm2_kernel<<<dim3(D_MODEL / GBN, T_SEQ / GBM), 256, GEMM2_SMEM>>>(
        Ohi, Olo, Wot, out, out, out, NQ, 0);
}

// round 10
// speedup vs baseline: 4.9816x; 1.0231x over previous
#include <cuda_runtime.h>
#include <cuda_bf16.h>
#include <cuda_fp16.h>
#include <math.h>
#include <math_constants.h>
#include <stdint.h>

#define T_SEQ   2048
#define D_MODEL 4096
#define NH      32
#define NKV     8
#define HD      128
#define NQ      (NH * HD)    // 4096
#define NKVD    (NKV * HD)   // 1024
#define NQKV    (NQ + 2 * NKVD)  // 6144

// ---------------- scratch (device globals; no allocations allowed) ----------------
__device__ float g_Q[T_SEQ * NQ];
__device__ float g_K[T_SEQ * NKVD];

__device__ __half g_Xhi[T_SEQ * D_MODEL];
__device__ __half g_Xlo[T_SEQ * D_MODEL];
__device__ __half g_Ohi[T_SEQ * NQ];
__device__ __half g_Olo[T_SEQ * NQ];
__device__ __half g_Wqkv[NQKV * D_MODEL];   // [6144][4096] fp16: Wq^T, Wk^T, Wv^T rows
__device__ __half g_Wot[D_MODEL * NQ];      // Wo^T fp16
__device__ __half g_Vh[T_SEQ * NKVD];       // V as fp16 (written by QKV GEMM epilogue)

__device__ __nv_bfloat16 g_Qhi[T_SEQ * NQ];
__device__ __nv_bfloat16 g_Qlo[T_SEQ * NQ];
__device__ __nv_bfloat16 g_Khi[T_SEQ * NKVD];
__device__ __nv_bfloat16 g_Klo[T_SEQ * NKVD];

__device__ float2 g_rope[T_SEQ * 64];       // (cos, sin) LUT

// ---------------- helpers ----------------
static __device__ __forceinline__ uint32_t smem_u32(const void* p) {
    uint32_t a;
    asm("{ .reg .u64 t; cvta.to.shared.u64 t, %1; cvt.u32.u64 %0, t; }" : "=r"(a) : "l"(p));
    return a;
}
static __device__ __forceinline__ void cp16(uint32_t s, const void* g) {
    asm volatile("cp.async.cg.shared.global [%0], [%1], 16;" :: "r"(s), "l"(g));
}
static __device__ __forceinline__ uint32_t pack_bf2(float a, float b) {
    __nv_bfloat162 t = __halves2bfloat162(__float2bfloat16(a), __float2bfloat16(b));
    return *(uint32_t*)&t;
}
static __device__ __forceinline__ uint32_t pack_h2(float a, float b) {
    __half2 t = __halves2half2(__float2half(a), __float2half(b));
    return *(uint32_t*)&t;
}

#define LDSM4(R, ADDR)                                                              \
    asm volatile("ldmatrix.sync.aligned.m8n8.x4.shared.b16 {%0,%1,%2,%3}, [%4];"    \
                 : "=r"((R)[0]), "=r"((R)[1]), "=r"((R)[2]), "=r"((R)[3])           \
                 : "r"(ADDR))

#define LDSM4T(R, ADDR)                                                             \
    asm volatile("ldmatrix.sync.aligned.m8n8.x4.trans.shared.b16 {%0,%1,%2,%3}, [%4];" \
                 : "=r"((R)[0]), "=r"((R)[1]), "=r"((R)[2]), "=r"((R)[3])           \
                 : "r"(ADDR))

#define MMA16816(C, A, B0, B1)                                                      \
    asm volatile("mma.sync.aligned.m16n8k16.row.col.f32.bf16.bf16.f32 "             \
                 "{%0,%1,%2,%3}, {%4,%5,%6,%7}, {%8,%9}, {%0,%1,%2,%3};"            \
                 : "+f"((C)[0]), "+f"((C)[1]), "+f"((C)[2]), "+f"((C)[3])           \
                 : "r"((A)[0]), "r"((A)[1]), "r"((A)[2]), "r"((A)[3]),              \
                   "r"(B0), "r"(B1))

#define MMAH16816(C, A, B0, B1)                                                     \
    asm volatile("mma.sync.aligned.m16n8k16.row.col.f32.f16.f16.f32 "               \
                 "{%0,%1,%2,%3}, {%4,%5,%6,%7}, {%8,%9}, {%0,%1,%2,%3};"            \
                 : "+f"((C)[0]), "+f"((C)[1]), "+f"((C)[2]), "+f"((C)[3])           \
                 : "r"((A)[0]), "r"((A)[1]), "r"((A)[2]), "r"((A)[3]),              \
                   "r"(B0), "r"(B1))

// ---------------- fp16 hi/lo split (elementwise) ----------------
__global__ __launch_bounds__(256) void splith_kernel(const float4* __restrict__ x,
                                                     __half* __restrict__ hi,
                                                     __half* __restrict__ lo, int n4) {
    int i = blockIdx.x * 256 + threadIdx.x;
    if (i >= n4) return;
    float4 v = x[i];
    float vs[4] = {v.x, v.y, v.z, v.w};
    __half h[4], l[4];
#pragma unroll
    for (int j = 0; j < 4; j++) {
        h[j] = __float2half(vs[j]);
        l[j] = __float2half(vs[j] - __half2float(h[j]));
    }
    __half2* hp = reinterpret_cast<__half2*>(hi) + 2 * (size_t)i;
    __half2* lp = reinterpret_cast<__half2*>(lo) + 2 * (size_t)i;
    hp[0] = __halves2half2(h[0], h[1]);
    hp[1] = __halves2half2(h[2], h[3]);
    lp[0] = __halves2half2(l[0], l[1]);
    lp[1] = __halves2half2(l[2], l[3]);
}

// ---------------- transpose to fp16: W[4096][N] -> dst[(row_off+n)][4096] ----------------
__global__ __launch_bounds__(256) void tf16_kernel(const float* __restrict__ W,
                                                   __half* __restrict__ dst,
                                                   int N, int row_off) {
    __shared__ float t[32][33];
    int n0 = blockIdx.x * 32, k0 = blockIdx.y * 32;
    int tx = threadIdx.x & 31, ty = threadIdx.x >> 5;
#pragma unroll
    for (int i = 0; i < 4; i++)
        t[ty + i * 8][tx] = W[(size_t)(k0 + ty + i * 8) * N + n0 + tx];
    __syncthreads();
#pragma unroll
    for (int i = 0; i < 4; i++) {
        int n = n0 + ty + i * 8, k = k0 + tx;
        dst[(size_t)(row_off + n) * D_MODEL + k] = __float2half(t[tx][ty + i * 8]);
    }
}

// ---------------- RoPE LUT (tiny; accurate trig computed once) ----------------
__global__ __launch_bounds__(64) void rope_lut_kernel() {
    int t = blockIdx.x, j = threadIdx.x;
    float inv_freq = 1.0f / powf(1000000.0f, (float)j * (1.0f / 64.0f));
    float ang = (float)t * inv_freq;
    g_rope[t * 64 + j] = make_float2(cosf(ang), sinf(ang));
}

// ---------------- fp16 2-pass GEMM, 128x256 tile ----------------
// C = (Ahi+Alo)[M,Kd] @ B[N,Kd]^T. 8 warps, warp tile 64x64, 1 CTA/SM.
#define GBM 128
#define GBN 256
#define GBK 32
#define SROW 80
#define G2A_HI 0
#define G2A_LO 10240
#define G2B    20480
#define G2STAGE 40960
#define GEMM2_SMEM (2 * G2STAGE)

__global__ __launch_bounds__(256, 1) void gemm2_kernel(
    const __half* __restrict__ Ahi, const __half* __restrict__ Alo,
    const __half* __restrict__ B,
    float* __restrict__ Cq, float* __restrict__ Ck, __half* __restrict__ Vh,
    int Kd, int qkv_mode) {
    extern __shared__ char smem[];
    const uint32_t sb = smem_u32(smem);
    const int tid = threadIdx.x, lane = tid & 31, wid = tid >> 5;
    const int m0 = blockIdx.y * GBM, n0 = blockIdx.x * GBN;

    const int wm = (wid & 1) * 64;
    const int wn = (wid >> 1) * 64;

    const uint32_t a_ro = (uint32_t)(wm + (lane & 15)) * SROW + ((lane >> 4) * 16);
    const uint32_t b_ro = (uint32_t)(wn + ((lane >> 4) << 3) + (lane & 7)) * SROW + (((lane >> 3) & 1) * 16);

    float acc[4][8][4];
#pragma unroll
    for (int a = 0; a < 4; a++)
#pragma unroll
        for (int b = 0; b < 8; b++)
#pragma unroll
            for (int c = 0; c < 4; c++) acc[a][b][c] = 0.0f;

    const int NC = Kd / GBK;

    auto stage_load = [&](int c, int st) {
        uint32_t s0 = sb + st * G2STAGE;
        int k0 = c * GBK;
#pragma unroll
        for (int i = 0; i < 2; i++) {
            int idx = tid + i * 256;          // 0..511: A rows
            int r = idx >> 2, seg = idx & 3;
            uint32_t so = (uint32_t)(r * SROW + seg * 16);
            cp16(s0 + G2A_HI + so, Ahi + (size_t)(m0 + r) * Kd + k0 + seg * 8);
            cp16(s0 + G2A_LO + so, Alo + (size_t)(m0 + r) * Kd + k0 + seg * 8);
        }
#pragma unroll
        for (int i = 0; i < 4; i++) {
            int idx = tid + i * 256;          // 0..1023: B rows
            int r = idx >> 2, seg = idx & 3;
            uint32_t so = (uint32_t)(r * SROW + seg * 16);
            cp16(s0 + G2B + so, B + (size_t)(n0 + r) * Kd + k0 + seg * 8);
        }
        asm volatile("cp.async.commit_group;" ::: "memory");
    };

    stage_load(0, 0);

    for (int c = 0; c < NC; ++c) {
        if (c + 1 < NC) {
            stage_load(c + 1, (c + 1) & 1);
            asm volatile("cp.async.wait_group 1;" ::: "memory");
        } else {
            asm volatile("cp.async.wait_group 0;" ::: "memory");
        }
        __syncthreads();

        const uint32_t s0 = sb + (c & 1) * G2STAGE;
#pragma unroll
        for (int ks = 0; ks < 2; ks++) {
            uint32_t ah[4][4], al[4][4], bh[4][4];
#pragma unroll
            for (int mf = 0; mf < 4; mf++) {
                uint32_t ao = a_ro + (uint32_t)(mf * 16) * SROW + ks * 32;
                LDSM4(ah[mf], s0 + G2A_HI + ao);
                LDSM4(al[mf], s0 + G2A_LO + ao);
            }
#pragma unroll
            for (int p = 0; p < 4; p++) {
                uint32_t bo = b_ro + (uint32_t)(p * 16) * SROW + ks * 32;
                LDSM4(bh[p], s0 + G2B + bo);
            }
#pragma unroll
            for (int mf = 0; mf < 4; mf++)
#pragma unroll
                for (int nf = 0; nf < 8; nf++) {
                    uint32_t b0 = bh[nf >> 1][(nf & 1) * 2], b1 = bh[nf >> 1][(nf & 1) * 2 + 1];
                    MMAH16816(acc[mf][nf], ah[mf], b0, b1);
                    MMAH16816(acc[mf][nf], al[mf], b0, b1);
                }
        }
        __syncthreads();
    }

    const int gid = lane >> 2, tig = lane & 3;

    if (qkv_mode && n0 >= NQ + NKVD) {
        // V region: write fp16 directly (no norm/rope on V)
        int coff = n0 - (NQ + NKVD);
#pragma unroll
        for (int mf = 0; mf < 4; mf++)
#pragma unroll
            for (int nf = 0; nf < 8; nf++) {
                int row = m0 + wm + mf * 16 + gid;
                int col = coff + wn + nf * 8 + tig * 2;
                *(uint32_t*)(Vh + (size_t)row * NKVD + col) = pack_h2(acc[mf][nf][0], acc[mf][nf][1]);
                *(uint32_t*)(Vh + (size_t)(row + 8) * NKVD + col) = pack_h2(acc[mf][nf][2], acc[mf][nf][3]);
            }
        return;
    }

    float* Cp;
    int ldc, coff;
    if (qkv_mode && n0 >= NQ) { Cp = Ck; ldc = NKVD; coff = n0 - NQ; }
    else                      { Cp = Cq; ldc = D_MODEL; coff = n0; }

#pragma unroll
    for (int mf = 0; mf < 4; mf++)
#pragma unroll
        for (int nf = 0; nf < 8; nf++) {
            int row = m0 + wm + mf * 16 + gid;
            int col = coff + wn + nf * 8 + tig * 2;
            float* cp0 = Cp + (size_t)row * ldc + col;
            float* cp1 = Cp + (size_t)(row + 8) * ldc + col;
            *(float2*)cp0 = make_float2(acc[mf][nf][0], acc[mf][nf][1]);
            *(float2*)cp1 = make_float2(acc[mf][nf][2], acc[mf][nf][3]);
        }
}

// ---------------- fused per-head RMSNorm + RoPE (LUT) -> bf16 hi/lo Q,K ----------------
__global__ __launch_bounds__(128) void rmsnorm_rope_kernel(const float* __restrict__ q_w,
                                                           const float* __restrict__ k_w) {
    const int t = blockIdx.x;
    const int hy = blockIdx.y;
    const int i = threadIdx.x;

    const float* base;
    const float* w;
    __nv_bfloat16 *oh, *ol;
    size_t off;
    if (hy < NH) {
        off = (size_t)t * NQ + hy * HD;
        base = g_Q + off; w = q_w; oh = g_Qhi + off; ol = g_Qlo + off;
    } else {
        off = (size_t)t * NKVD + (hy - NH) * HD;
        base = g_K + off; w = k_w; oh = g_Khi + off; ol = g_Klo + off;
    }

    float x = base[i];
    float v = x * x;
#pragma unroll
    for (int o = 16; o > 0; o >>= 1) v += __shfl_xor_sync(0xffffffffu, v, o);
    __shared__ float ws[4];
    const int lane = i & 31, wid = i >> 5;
    if (lane == 0) ws[wid] = v;
    __syncthreads();
    float sum = ws[0] + ws[1] + ws[2] + ws[3];

    float r = rsqrtf(sum * (1.0f / HD) + 1e-6f);
    float xn = w[i] * (x * r);

    __shared__ float sh[HD];
    sh[i] = xn;
    __syncthreads();

    float2 cs = g_rope[t * 64 + (i & 63)];
    float rot = (i < 64) ? -sh[i + 64] : sh[i - 64];
    float y = xn * cs.x + rot * cs.y;

    __nv_bfloat16 hb = __float2bfloat16(y);
    oh[i] = hb;
    ol[i] = __float2bfloat16(y - __bfloat162float(hb));
}

// ---------------- HMMA causal flash attention ----------------
// S: bf16 3-pass (logit-safe). PV: fp16 2-pass (P hi/lo, single fp16 V).
#define A_SROW 272
#define AQH 0
#define AQL 17408
#define AKH 34816
#define AKL 52224
#define AVH 69632
#define ATTN_SMEM 87040

__global__ __launch_bounds__(128, 2) void attn_kernel(
    const __nv_bfloat16* __restrict__ Qh, const __nv_bfloat16* __restrict__ Ql,
    const __nv_bfloat16* __restrict__ Kh, const __nv_bfloat16* __restrict__ Kl,
    const __half* __restrict__ Vh,
    __half* __restrict__ Ohi, __half* __restrict__ Olo) {
    extern __shared__ char smc[];
    const uint32_t sb = smem_u32(smc);
    const int tid = threadIdx.x, lane = tid & 31, wid = tid >> 5;
    const int qtile = blockIdx.x, h = blockIdx.y;
    const int q0 = qtile * 64, kvh = h >> 2;
    const int gid = lane >> 2, tig = lane & 3, wm = wid * 16;

    const uint32_t a_ro = (uint32_t)(wm + (lane & 15)) * A_SROW + ((lane >> 4) * 16);
    const uint32_t b_ro = (uint32_t)(((lane >> 4) << 3) + (lane & 7)) * A_SROW + (((lane >> 3) & 1) * 16);
    const uint32_t v_ro = (uint32_t)((((lane >> 3) & 1) * 8) + (lane & 7)) * A_SROW + ((lane >> 4) * 16);

#pragma unroll
    for (int i = 0; i < 8; i++) {
        int idx = tid + i * 128;
        int r = idx >> 4, sg = idx & 15;
        uint32_t so = (uint32_t)(r * A_SROW + sg * 16);
        size_t go = (size_t)(q0 + r) * NQ + h * HD + sg * 8;
        cp16(sb + AQH + so, Qh + go);
        cp16(sb + AQL + so, Ql + go);
    }
    asm volatile("cp.async.commit_group;" ::: "memory");

    float o[16][4];
#pragma unroll
    for (int a = 0; a < 16; a++)
#pragma unroll
        for (int b = 0; b < 4; b++) o[a][b] = 0.0f;
    float m_i[2] = {-1e30f, -1e30f}, l_i[2] = {0.0f, 0.0f};
    const float scale = 0.08838834764831845f;

    const int ntiles = qtile + 1;
    for (int kt = 0; kt < ntiles; kt++) {
        const int k0 = kt * 64;
        __syncthreads();
#pragma unroll
        for (int i = 0; i < 8; i++) {
            int idx = tid + i * 128;
            int r = idx >> 4, sg = idx & 15;
            uint32_t so = (uint32_t)(r * A_SROW + sg * 16);
            size_t go = (size_t)(k0 + r) * NKVD + kvh * HD + sg * 8;
            cp16(sb + AKH + so, Kh + go);
            cp16(sb + AKL + so, Kl + go);
            cp16(sb + AVH + so, Vh + go);
        }
        asm volatile("cp.async.commit_group;" ::: "memory");
        asm volatile("cp.async.wait_group 0;" ::: "memory");
        __syncthreads();

        float s[8][4];
#pragma unroll
        for (int nf = 0; nf < 8; nf++)
#pragma unroll
            for (int e = 0; e < 4; e++) s[nf][e] = 0.0f;

#pragma unroll
        for (int ks = 0; ks < 8; ks++) {
            uint32_t ah[4], al[4], bh[4][4], bl[4][4];
            uint32_t ao = a_ro + ks * 32;
            LDSM4(ah, sb + AQH + ao);
            LDSM4(al, sb + AQL + ao);
#pragma unroll
            for (int p = 0; p < 4; p++) {
                uint32_t bo = b_ro + (uint32_t)(p * 16) * A_SROW + ks * 32;
                LDSM4(bh[p], sb + AKH + bo);
                LDSM4(bl[p], sb + AKL + bo);
            }
#pragma unroll
            for (int nf = 0; nf < 8; nf++) {
                uint32_t h0 = bh[nf >> 1][(nf & 1) * 2], h1 = bh[nf >> 1][(nf & 1) * 2 + 1];
                uint32_t l0 = bl[nf >> 1][(nf & 1) * 2], l1 = bl[nf >> 1][(nf & 1) * 2 + 1];
                MMA16816(s[nf], ah, h0, h1);
                MMA16816(s[nf], al, h0, h1);
                MMA16816(s[nf], ah, l0, l1);
            }
        }

        const bool diag = (kt == qtile);
#pragma unroll
        for (int nf = 0; nf < 8; nf++)
#pragma unroll
            for (int e = 0; e < 4; e++) {
                float v = s[nf][e] * scale;
                if (diag) {
                    int row = wm + gid + ((e >> 1) << 3);
                    int col = nf * 8 + tig * 2 + (e & 1);
                    if (col > row) v = -1e30f;
                }
                s[nf][e] = v;
            }

        float fac[2];
#pragma unroll
        for (int r = 0; r < 2; r++) {
            float mx = -1e30f;
#pragma unroll
            for (int nf = 0; nf < 8; nf++)
                mx = fmaxf(mx, fmaxf(s[nf][r * 2], s[nf][r * 2 + 1]));
            mx = fmaxf(mx, __shfl_xor_sync(0xffffffffu, mx, 1));
            mx = fmaxf(mx, __shfl_xor_sync(0xffffffffu, mx, 2));
            float mn = fmaxf(m_i[r], mx);
            fac[r] = __expf(m_i[r] - mn);
            m_i[r] = mn;
            l_i[r] *= fac[r];
        }
#pragma unroll
        for (int nf = 0; nf < 16; nf++) {
            o[nf][0] *= fac[0]; o[nf][1] *= fac[0];
            o[nf][2] *= fac[1]; o[nf][3] *= fac[1];
        }
        float rs[2] = {0.0f, 0.0f};
#pragma unroll
        for (int nf = 0; nf < 8; nf++)
#pragma unroll
            for (int e = 0; e < 4; e++) {
                float p = __expf(s[nf][e] - m_i[e >> 1]);
                s[nf][e] = p;
                rs[e >> 1] += p;
            }
#pragma unroll
        for (int r = 0; r < 2; r++) {
            rs[r] += __shfl_xor_sync(0xffffffffu, rs[r], 1);
            rs[r] += __shfl_xor_sync(0xffffffffu, rs[r], 2);
            l_i[r] += rs[r];
        }

        // repack P (C-frag -> A-frag) as fp16 hi/lo
        uint32_t ph[4][4], pl[4][4];
#pragma unroll
        for (int kf = 0; kf < 4; kf++) {
            float* f0 = s[2 * kf];
            float* f1 = s[2 * kf + 1];
            float v0[8] = {f0[0], f0[1], f0[2], f0[3], f1[0], f1[1], f1[2], f1[3]};
            float r0[8];
#pragma unroll
            for (int q = 0; q < 8; q++) {
                __half hb = __float2half(v0[q]);
                r0[q] = v0[q] - __half2float(hb);
            }
            ph[kf][0] = pack_h2(v0[0], v0[1]);
            ph[kf][1] = pack_h2(v0[2], v0[3]);
            ph[kf][2] = pack_h2(v0[4], v0[5]);
            ph[kf][3] = pack_h2(v0[6], v0[7]);
            pl[kf][0] = pack_h2(r0[0], r0[1]);
            pl[kf][1] = pack_h2(r0[2], r0[3]);
            pl[kf][2] = pack_h2(r0[4], r0[5]);
            pl[kf][3] = pack_h2(r0[6], r0[7]);
        }

        // O += P V (fp16 2-pass, single fp16 V via ldmatrix.trans)
#pragma unroll
        for (int kf = 0; kf < 4; kf++) {
#pragma unroll
            for (int j = 0; j < 8; j++) {
                uint32_t vh4[4];
                uint32_t vo = v_ro + (uint32_t)(kf * 16) * A_SROW + j * 32;
                LDSM4T(vh4, sb + AVH + vo);
                MMAH16816(o[2 * j], ph[kf], vh4[0], vh4[1]);
                MMAH16816(o[2 * j], pl[kf], vh4[0], vh4[1]);
                MMAH16816(o[2 * j + 1], ph[kf], vh4[2], vh4[3]);
                MMAH16816(o[2 * j + 1], pl[kf], vh4[2], vh4[3]);
            }
        }
    }

    // epilogue: normalize, split to fp16 hi/lo, store
    float inv[2] = {1.0f / l_i[0], 1.0f / l_i[1]};
    int row0 = q0 + wm + gid;
#pragma unroll
    for (int nf = 0; nf < 16; nf++) {
        int col = h * HD + nf * 8 + tig * 2;
#pragma unroll
        for (int r = 0; r < 2; r++) {
            float o0 = o[nf][r * 2] * inv[r];
            float o1 = o[nf][r * 2 + 1] * inv[r];
            __half h0 = __float2half(o0), h1 = __float2half(o1);
            float l0 = o0 - __half2float(h0), l1 = o1 - __half2float(h1);
            size_t base = (size_t)(row0 + r * 8) * NQ + col;
            *(__half2*)(Ohi + base) = __halves2half2(h0, h1);
            *(__half2*)(Olo + base) = __halves2half2(__float2half(l0), __float2half(l1));
        }
    }
}

// ---------------- launcher ----------------
extern "C" void kernel_launch(void* const* d_in, const int* in_sizes, int n_in,
                              void* d_out, int out_size) {
    const float* x  = (const float*)d_in[0];
    const float* Wq = (const float*)d_in[1];
    const float* Wk = (const float*)d_in[2];
    const float* Wv = (const float*)d_in[3];
    const float* Wo = (const float*)d_in[4];
    const float* qw = (const float*)d_in[5];
    const float* kw = (const float*)d_in[6];
    float* out = (float*)d_out;

    float *Qb, *Kb;
    cudaGetSymbolAddress((void**)&Qb, g_Q);
    cudaGetSymbolAddress((void**)&Kb, g_K);
    __half *Xhi, *Xlo, *Ohi, *Olo, *Wqkv, *Wot, *Vh;
    cudaGetSymbolAddress((void**)&Xhi, g_Xhi);
    cudaGetSymbolAddress((void**)&Xlo, g_Xlo);
    cudaGetSymbolAddress((void**)&Ohi, g_Ohi);
    cudaGetSymbolAddress((void**)&Olo, g_Olo);
    cudaGetSymbolAddress((void**)&Wqkv, g_Wqkv);
    cudaGetSymbolAddress((void**)&Wot, g_Wot);
    cudaGetSymbolAddress((void**)&Vh, g_Vh);
    __nv_bfloat16 *Qhi, *Qlo, *Khi, *Klo;
    cudaGetSymbolAddress((void**)&Qhi, g_Qhi);
    cudaGetSymbolAddress((void**)&Qlo, g_Qlo);
    cudaGetSymbolAddress((void**)&Khi, g_Khi);
    cudaGetSymbolAddress((void**)&Klo, g_Klo);

    cudaFuncSetAttribute(gemm2_kernel, cudaFuncAttributeMaxDynamicSharedMemorySize, GEMM2_SMEM);
    cudaFuncSetAttribute(attn_kernel, cudaFuncAttributeMaxDynamicSharedMemorySize, ATTN_SMEM);

    // 1. prep: X split, weights transpose, RoPE LUT
    int n4x = T_SEQ * D_MODEL / 4;
    splith_kernel<<<(n4x + 255) / 256, 256>>>((const float4*)x, Xhi, Xlo, n4x);
    tf16_kernel<<<dim3(NQ / 32, D_MODEL / 32), 256>>>(Wq, Wqkv, NQ, 0);
    tf16_kernel<<<dim3(NKVD / 32, D_MODEL / 32), 256>>>(Wk, Wqkv, NKVD, NQ);
    tf16_kernel<<<dim3(NKVD / 32, D_MODEL / 32), 256>>>(Wv, Wqkv, NKVD, NQ + NKVD);
    tf16_kernel<<<dim3(NQ / 32, D_MODEL / 32), 256>>>(Wo, Wot, NQ, 0);
    rope_lut_kernel<<<T_SEQ, 64>>>();

    // 2. merged QKV projection (V written as fp16 directly)
    gemm2_kernel<<<dim3(NQKV / GBN, T_SEQ / GBM), 256, GEMM2_SMEM>>>(
        Xhi, Xlo, Wqkv, Qb, Kb, Vh, D_MODEL, 1);

    // 3. RMSNorm + RoPE -> bf16 hi/lo Q,K
    rmsnorm_rope_kernel<<<dim3(T_SEQ, NH + NKV), 128>>>(qw, kw);

    // 4. HMMA causal flash attention -> fp16 hi/lo O
    attn_kernel<<<dim3(T_SEQ / 64, NH), 128, ATTN_SMEM>>>(Qhi, Qlo, Khi, Klo, Vh, Ohi, Olo);

    // 5. output projection
    gemm2_kernel<<<dim3(D_MODEL / GBN, T_SEQ / GBM), 256, GEMM2_SMEM>>>(
        Ohi, Olo, Wot, out, out, (__half*)Vh, NQ, 0);
}

// round 15
// speedup vs baseline: 5.0279x; 1.0093x over previous
#include <cuda_runtime.h>
#include <cuda_bf16.h>
#include <cuda_fp16.h>
#include <math.h>
#include <math_constants.h>
#include <stdint.h>

#define T_SEQ   2048
#define D_MODEL 4096
#define NH      32
#define NKV     8
#define HD      128
#define NQ      (NH * HD)    // 4096
#define NKVD    (NKV * HD)   // 1024
#define NQKV    (NQ + 2 * NKVD)  // 6144

// ---------------- scratch (device globals; no allocations allowed) ----------------
__device__ float g_Q[T_SEQ * NQ];
__device__ float g_K[T_SEQ * NKVD];

__device__ __half g_Xhi[T_SEQ * D_MODEL];
__device__ __half g_Xlo[T_SEQ * D_MODEL];
__device__ __half g_Ohi[T_SEQ * NQ];
__device__ __half g_Olo[T_SEQ * NQ];
__device__ __half g_Wqkv[NQKV * D_MODEL];   // fp16: Wq^T, Wk^T, Wv^T rows
__device__ __half g_Wot[D_MODEL * NQ];      // Wo^T fp16
__device__ __half g_Vh[T_SEQ * NKVD];       // V fp16 (written by QKV GEMM epilogue)

__device__ __nv_bfloat16 g_Qhi[T_SEQ * NQ];
__device__ __nv_bfloat16 g_Qlo[T_SEQ * NQ];
__device__ __nv_bfloat16 g_Khi[T_SEQ * NKVD];
__device__ __nv_bfloat16 g_Klo[T_SEQ * NKVD];

__device__ float2 g_rope[T_SEQ * 64];       // (cos, sin) LUT

// ---------------- helpers ----------------
static __device__ __forceinline__ uint32_t smem_u32(const void* p) {
    uint32_t a;
    asm("{ .reg .u64 t; cvta.to.shared.u64 t, %1; cvt.u32.u64 %0, t; }" : "=r"(a) : "l"(p));
    return a;
}
static __device__ __forceinline__ void cp16(uint32_t s, const void* g) {
    asm volatile("cp.async.cg.shared.global [%0], [%1], 16;" :: "r"(s), "l"(g));
}
static __device__ __forceinline__ uint32_t pack_h2(float a, float b) {
    __half2 t = __halves2half2(__float2half(a), __float2half(b));
    return *(uint32_t*)&t;
}

#define LDSM4(R, ADDR)                                                              \
    asm volatile("ldmatrix.sync.aligned.m8n8.x4.shared.b16 {%0,%1,%2,%3}, [%4];"    \
                 : "=r"((R)[0]), "=r"((R)[1]), "=r"((R)[2]), "=r"((R)[3])           \
                 : "r"(ADDR))

#define LDSM4T(R, ADDR)                                                             \
    asm volatile("ldmatrix.sync.aligned.m8n8.x4.trans.shared.b16 {%0,%1,%2,%3}, [%4];" \
                 : "=r"((R)[0]), "=r"((R)[1]), "=r"((R)[2]), "=r"((R)[3])           \
                 : "r"(ADDR))

#define MMA16816(C, A, B0, B1)                                                      \
    asm volatile("mma.sync.aligned.m16n8k16.row.col.f32.bf16.bf16.f32 "             \
                 "{%0,%1,%2,%3}, {%4,%5,%6,%7}, {%8,%9}, {%0,%1,%2,%3};"            \
                 : "+f"((C)[0]), "+f"((C)[1]), "+f"((C)[2]), "+f"((C)[3])           \
                 : "r"((A)[0]), "r"((A)[1]), "r"((A)[2]), "r"((A)[3]),              \
                   "r"(B0), "r"(B1))

#define MMAH16816(C, A, B0, B1)                                                     \
    asm volatile("mma.sync.aligned.m16n8k16.row.col.f32.f16.f16.f32 "               \
                 "{%0,%1,%2,%3}, {%4,%5,%6,%7}, {%8,%9}, {%0,%1,%2,%3};"            \
                 : "+f"((C)[0]), "+f"((C)[1]), "+f"((C)[2]), "+f"((C)[3])           \
                 : "r"((A)[0]), "r"((A)[1]), "r"((A)[2]), "r"((A)[3]),              \
                   "r"(B0), "r"(B1))

// ---------------- fp16 hi/lo split ----------------
__global__ __launch_bounds__(256) void splith_kernel(const float4* __restrict__ x,
                                                     __half* __restrict__ hi,
                                                     __half* __restrict__ lo, int n4) {
    int i = blockIdx.x * 256 + threadIdx.x;
    if (i >= n4) return;
    float4 v = x[i];
    float vs[4] = {v.x, v.y, v.z, v.w};
    __half h[4], l[4];
#pragma unroll
    for (int j = 0; j < 4; j++) {
        h[j] = __float2half(vs[j]);
        l[j] = __float2half(vs[j] - __half2float(h[j]));
    }
    __half2* hp = reinterpret_cast<__half2*>(hi) + 2 * (size_t)i;
    __half2* lp = reinterpret_cast<__half2*>(lo) + 2 * (size_t)i;
    hp[0] = __halves2half2(h[0], h[1]);
    hp[1] = __halves2half2(h[2], h[3]);
    lp[0] = __halves2half2(l[0], l[1]);
    lp[1] = __halves2half2(l[2], l[3]);
}

// ---------------- transpose to fp16 ----------------
__global__ __launch_bounds__(256) void tf16_kernel(const float* __restrict__ W,
                                                   __half* __restrict__ dst,
                                                   int N, int row_off) {
    __shared__ float t[32][33];
    int n0 = blockIdx.x * 32, k0 = blockIdx.y * 32;
    int tx = threadIdx.x & 31, ty = threadIdx.x >> 5;
#pragma unroll
    for (int i = 0; i < 4; i++)
        t[ty + i * 8][tx] = W[(size_t)(k0 + ty + i * 8) * N + n0 + tx];
    __syncthreads();
#pragma unroll
    for (int i = 0; i < 4; i++) {
        int n = n0 + ty + i * 8, k = k0 + tx;
        dst[(size_t)(row_off + n) * D_MODEL + k] = __float2half(t[tx][ty + i * 8]);
    }
}

// ---------------- RoPE LUT ----------------
__global__ __launch_bounds__(64) void rope_lut_kernel() {
    int t = blockIdx.x, j = threadIdx.x;
    float inv_freq = 1.0f / powf(1000000.0f, (float)j * (1.0f / 64.0f));
    float ang = (float)t * inv_freq;
    g_rope[t * 64 + j] = make_float2(cosf(ang), sinf(ang));
}

// ---------------- fp16 2-pass GEMM, 128x256 tile, 4-stage pipeline ----------------
#define GBM 128
#define GBN 256
#define GBK 32
#define SROW 80
#define G2A_HI 0
#define G2A_LO 10240
#define G2B    20480
#define G2STAGE 40960
#define G2NST  4
#define GEMM2_SMEM (G2NST * G2STAGE)

__global__ __launch_bounds__(256, 1) void gemm2_kernel(
    const __half* __restrict__ Ahi, const __half* __restrict__ Alo,
    const __half* __restrict__ B,
    float* __restrict__ Cq, float* __restrict__ Ck, __half* __restrict__ Vh,
    int Kd, int qkv_mode) {
    extern __shared__ char smem[];
    const uint32_t sb = smem_u32(smem);
    const int tid = threadIdx.x, lane = tid & 31, wid = tid >> 5;
    const int m0 = blockIdx.y * GBM, n0 = blockIdx.x * GBN;

    const int wm = (wid & 1) * 64;
    const int wn = (wid >> 1) * 64;

    const uint32_t a_ro = (uint32_t)(wm + (lane & 15)) * SROW + ((lane >> 4) * 16);
    const uint32_t b_ro = (uint32_t)(wn + ((lane >> 4) << 3) + (lane & 7)) * SROW + (((lane >> 3) & 1) * 16);

    float acc[4][8][4];
#pragma unroll
    for (int a = 0; a < 4; a++)
#pragma unroll
        for (int b = 0; b < 8; b++)
#pragma unroll
            for (int c = 0; c < 4; c++) acc[a][b][c] = 0.0f;

    const int NC = Kd / GBK;

    auto stage_load = [&](int c, int st) {
        uint32_t s0 = sb + st * G2STAGE;
        int k0 = c * GBK;
#pragma unroll
        for (int i = 0; i < 2; i++) {
            int idx = tid + i * 256;          // A rows (128 rows x 4 segs = 512)
            int r = idx >> 2, seg = idx & 3;
            uint32_t so = (uint32_t)(r * SROW + seg * 16);
            cp16(s0 + G2A_HI + so, Ahi + (size_t)(m0 + r) * Kd + k0 + seg * 8);
            cp16(s0 + G2A_LO + so, Alo + (size_t)(m0 + r) * Kd + k0 + seg * 8);
        }
#pragma unroll
        for (int i = 0; i < 4; i++) {
            int idx = tid + i * 256;          // B rows (256 rows x 4 segs = 1024)
            int r = idx >> 2, seg = idx & 3;
            uint32_t so = (uint32_t)(r * SROW + seg * 16);
            cp16(s0 + G2B + so, B + (size_t)(n0 + r) * Kd + k0 + seg * 8);
        }
        asm volatile("cp.async.commit_group;" ::: "memory");
    };

    // prologue: fill 3 stages
    stage_load(0, 0);
    stage_load(1, 1);
    stage_load(2, 2);

    for (int c = 0; c < NC; ++c) {
        asm volatile("cp.async.wait_group 2;" ::: "memory");   // stage c landed
        __syncthreads();

        // keep exactly one commit per iteration (group accounting)
        if (c + 3 < NC) stage_load(c + 3, (c + 3) & 3);
        else            asm volatile("cp.async.commit_group;" ::: "memory");

        const uint32_t s0 = sb + (c & 3) * G2STAGE;
#pragma unroll
        for (int ks = 0; ks < 2; ks++) {
            uint32_t ah[4][4], al[4][4], bh[4][4];
#pragma unroll
            for (int mf = 0; mf < 4; mf++) {
                uint32_t ao = a_ro + (uint32_t)(mf * 16) * SROW + ks * 32;
                LDSM4(ah[mf], s0 + G2A_HI + ao);
                LDSM4(al[mf], s0 + G2A_LO + ao);
            }
#pragma unroll
            for (int p = 0; p < 4; p++) {
                uint32_t bo = b_ro + (uint32_t)(p * 16) * SROW + ks * 32;
                LDSM4(bh[p], s0 + G2B + bo);
            }
#pragma unroll
            for (int mf = 0; mf < 4; mf++)
#pragma unroll
                for (int nf = 0; nf < 8; nf++) {
                    uint32_t b0 = bh[nf >> 1][(nf & 1) * 2], b1 = bh[nf >> 1][(nf & 1) * 2 + 1];
                    MMAH16816(acc[mf][nf], ah[mf], b0, b1);
                    MMAH16816(acc[mf][nf], al[mf], b0, b1);
                }
        }
    }

    const int gid = lane >> 2, tig = lane & 3;

    if (qkv_mode && n0 >= NQ + NKVD) {
        int coff = n0 - (NQ + NKVD);
#pragma unroll
        for (int mf = 0; mf < 4; mf++)
#pragma unroll
            for (int nf = 0; nf < 8; nf++) {
                int row = m0 + wm + mf * 16 + gid;
                int col = coff + wn + nf * 8 + tig * 2;
                *(uint32_t*)(Vh + (size_t)row * NKVD + col) = pack_h2(acc[mf][nf][0], acc[mf][nf][1]);
                *(uint32_t*)(Vh + (size_t)(row + 8) * NKVD + col) = pack_h2(acc[mf][nf][2], acc[mf][nf][3]);
            }
        return;
    }

    float* Cp;
    int ldc, coff;
    if (qkv_mode && n0 >= NQ) { Cp = Ck; ldc = NKVD; coff = n0 - NQ; }
    else                      { Cp = Cq; ldc = D_MODEL; coff = n0; }

#pragma unroll
    for (int mf = 0; mf < 4; mf++)
#pragma unroll
        for (int nf = 0; nf < 8; nf++) {
            int row = m0 + wm + mf * 16 + gid;
            int col = coff + wn + nf * 8 + tig * 2;
            float* cp0 = Cp + (size_t)row * ldc + col;
            float* cp1 = Cp + (size_t)(row + 8) * ldc + col;
            *(float2*)cp0 = make_float2(acc[mf][nf][0], acc[mf][nf][1]);
            *(float2*)cp1 = make_float2(acc[mf][nf][2], acc[mf][nf][3]);
        }
}

// ---------------- fused per-head RMSNorm + RoPE (LUT) -> bf16 hi/lo Q,K ----------------
__global__ __launch_bounds__(128) void rmsnorm_rope_kernel(const float* __restrict__ q_w,
                                                           const float* __restrict__ k_w) {
    const int t = blockIdx.x;
    const int hy = blockIdx.y;
    const int i = threadIdx.x;

    const float* base;
    const float* w;
    __nv_bfloat16 *oh, *ol;
    size_t off;
    if (hy < NH) {
        off = (size_t)t * NQ + hy * HD;
        base = g_Q + off; w = q_w; oh = g_Qhi + off; ol = g_Qlo + off;
    } else {
        off = (size_t)t * NKVD + (hy - NH) * HD;
        base = g_K + off; w = k_w; oh = g_Khi + off; ol = g_Klo + off;
    }

    float x = base[i];
    float v = x * x;
#pragma unroll
    for (int o = 16; o > 0; o >>= 1) v += __shfl_xor_sync(0xffffffffu, v, o);
    __shared__ float ws[4];
    const int lane = i & 31, wid = i >> 5;
    if (lane == 0) ws[wid] = v;
    __syncthreads();
    float sum = ws[0] + ws[1] + ws[2] + ws[3];

    float r = rsqrtf(sum * (1.0f / HD) + 1e-6f);
    float xn = w[i] * (x * r);

    __shared__ float sh[HD];
    sh[i] = xn;
    __syncthreads();

    float2 cs = g_rope[t * 64 + (i & 63)];
    float rot = (i < 64) ? -sh[i + 64] : sh[i - 64];
    float y = xn * cs.x + rot * cs.y;

    __nv_bfloat16 hb = __float2bfloat16(y);
    oh[i] = hb;
    ol[i] = __float2bfloat16(y - __bfloat162float(hb));
}

// ---------------- HMMA causal flash attention ----------------
#define A_SROW 272
#define AQH 0
#define AQL 17408
#define AKH 34816
#define AKL 52224
#define AVH 69632
#define ATTN_SMEM 87040

__global__ __launch_bounds__(128, 2) void attn_kernel(
    const __nv_bfloat16* __restrict__ Qh, const __nv_bfloat16* __restrict__ Ql,
    const __nv_bfloat16* __restrict__ Kh, const __nv_bfloat16* __restrict__ Kl,
    const __half* __restrict__ Vh,
    __half* __restrict__ Ohi, __half* __restrict__ Olo) {
    extern __shared__ char smc[];
    const uint32_t sb = smem_u32(smc);
    const int tid = threadIdx.x, lane = tid & 31, wid = tid >> 5;
    const int qtile = blockIdx.x, h = blockIdx.y;
    const int q0 = qtile * 64, kvh = h >> 2;
    const int gid = lane >> 2, tig = lane & 3, wm = wid * 16;

    const uint32_t a_ro = (uint32_t)(wm + (lane & 15)) * A_SROW + ((lane >> 4) * 16);
    const uint32_t b_ro = (uint32_t)(((lane >> 4) << 3) + (lane & 7)) * A_SROW + (((lane >> 3) & 1) * 16);
    const uint32_t v_ro = (uint32_t)((((lane >> 3) & 1) * 8) + (lane & 7)) * A_SROW + ((lane >> 4) * 16);

#pragma unroll
    for (int i = 0; i < 8; i++) {
        int idx = tid + i * 128;
        int r = idx >> 4, sg = idx & 15;
        uint32_t so = (uint32_t)(r * A_SROW + sg * 16);
        size_t go = (size_t)(q0 + r) * NQ + h * HD + sg * 8;
        cp16(sb + AQH + so, Qh + go);
        cp16(sb + AQL + so, Ql + go);
    }
    asm volatile("cp.async.commit_group;" ::: "memory");

    float o[16][4];
#pragma unroll
    for (int a = 0; a < 16; a++)
#pragma unroll
        for (int b = 0; b < 4; b++) o[a][b] = 0.0f;
    float m_i[2] = {-1e30f, -1e30f}, l_i[2] = {0.0f, 0.0f};
    const float scale = 0.08838834764831845f;

    const int ntiles = qtile + 1;
    for (int kt = 0; kt < ntiles; kt++) {
        const int k0 = kt * 64;
        __syncthreads();
#pragma unroll
        for (int i = 0; i < 8; i++) {
            int idx = tid + i * 128;
            int r = idx >> 4, sg = idx & 15;
            uint32_t so = (uint32_t)(r * A_SROW + sg * 16);
            size_t go = (size_t)(k0 + r) * NKVD + kvh * HD + sg * 8;
            cp16(sb + AKH + so, Kh + go);
            cp16(sb + AKL + so, Kl + go);
            cp16(sb + AVH + so, Vh + go);
        }
        asm volatile("cp.async.commit_group;" ::: "memory");
        asm volatile("cp.async.wait_group 0;" ::: "memory");
        __syncthreads();

        float s[8][4];
#pragma unroll
        for (int nf = 0; nf < 8; nf++)
#pragma unroll
            for (int e = 0; e < 4; e++) s[nf][e] = 0.0f;

#pragma unroll
        for (int ks = 0; ks < 8; ks++) {
            uint32_t ah[4], al[4], bh[4][4], bl[4][4];
            uint32_t ao = a_ro + ks * 32;
            LDSM4(ah, sb + AQH + ao);
            LDSM4(al, sb + AQL + ao);
#pragma unroll
            for (int p = 0; p < 4; p++) {
                uint32_t bo = b_ro + (uint32_t)(p * 16) * A_SROW + ks * 32;
                LDSM4(bh[p], sb + AKH + bo);
                LDSM4(bl[p], sb + AKL + bo);
            }
#pragma unroll
            for (int nf = 0; nf < 8; nf++) {
                uint32_t h0 = bh[nf >> 1][(nf & 1) * 2], h1 = bh[nf >> 1][(nf & 1) * 2 + 1];
                uint32_t l0 = bl[nf >> 1][(nf & 1) * 2], l1 = bl[nf >> 1][(nf & 1) * 2 + 1];
                MMA16816(s[nf], ah, h0, h1);
                MMA16816(s[nf], al, h0, h1);
                MMA16816(s[nf], ah, l0, l1);
            }
        }

        const bool diag = (kt == qtile);
#pragma unroll
        for (int nf = 0; nf < 8; nf++)
#pragma unroll
            for (int e = 0; e < 4; e++) {
                float v = s[nf][e] * scale;
                if (diag) {
                    int row = wm + gid + ((e >> 1) << 3);
                    int col = nf * 8 + tig * 2 + (e & 1);
                    if (col > row) v = -1e30f;
                }
                s[nf][e] = v;
            }

        float fac[2];
#pragma unroll
        for (int r = 0; r < 2; r++) {
            float mx = -1e30f;
#pragma unroll
            for (int nf = 0; nf < 8; nf++)
                mx = fmaxf(mx, fmaxf(s[nf][r * 2], s[nf][r * 2 + 1]));
            mx = fmaxf(mx, __shfl_xor_sync(0xffffffffu, mx, 1));
            mx = fmaxf(mx, __shfl_xor_sync(0xffffffffu, mx, 2));
            float mn = fmaxf(m_i[r], mx);
            fac[r] = __expf(m_i[r] - mn);
            m_i[r] = mn;
            l_i[r] *= fac[r];
        }
#pragma unroll
        for (int nf = 0; nf < 16; nf++) {
            o[nf][0] *= fac[0]; o[nf][1] *= fac[0];
            o[nf][2] *= fac[1]; o[nf][3] *= fac[1];
        }
        float rs[2] = {0.0f, 0.0f};
#pragma unroll
        for (int nf = 0; nf < 8; nf++)
#pragma unroll
            for (int e = 0; e < 4; e++) {
                float p = __expf(s[nf][e] - m_i[e >> 1]);
                s[nf][e] = p;
                rs[e >> 1] += p;
            }
#pragma unroll
        for (int r = 0; r < 2; r++) {
            rs[r] += __shfl_xor_sync(0xffffffffu, rs[r], 1);
            rs[r] += __shfl_xor_sync(0xffffffffu, rs[r], 2);
            l_i[r] += rs[r];
        }

        uint32_t ph[4][4], pl[4][4];
#pragma unroll
        for (int kf = 0; kf < 4; kf++) {
            float* f0 = s[2 * kf];
            float* f1 = s[2 * kf + 1];
            float v0[8] = {f0[0], f0[1], f0[2], f0[3], f1[0], f1[1], f1[2], f1[3]};
            float r0[8];
#pragma unroll
            for (int q = 0; q < 8; q++) {
                __half hb = __float2half(v0[q]);
                r0[q] = v0[q] - __half2float(hb);
            }
            ph[kf][0] = pack_h2(v0[0], v0[1]);
            ph[kf][1] = pack_h2(v0[2], v0[3]);
            ph[kf][2] = pack_h2(v0[4], v0[5]);
            ph[kf][3] = pack_h2(v0[6], v0[7]);
            pl[kf][0] = pack_h2(r0[0], r0[1]);
            pl[kf][1] = pack_h2(r0[2], r0[3]);
            pl[kf][2] = pack_h2(r0[4], r0[5]);
            pl[kf][3] = pack_h2(r0[6], r0[7]);
        }

#pragma unroll
        for (int kf = 0; kf < 4; kf++) {
#pragma unroll
            for (int j = 0; j < 8; j++) {
                uint32_t vh4[4];
                uint32_t vo = v_ro + (uint32_t)(kf * 16) * A_SROW + j * 32;
                LDSM4T(vh4, sb + AVH + vo);
                MMAH16816(o[2 * j], ph[kf], vh4[0], vh4[1]);
                MMAH16816(o[2 * j], pl[kf], vh4[0], vh4[1]);
                MMAH16816(o[2 * j + 1], ph[kf], vh4[2], vh4[3]);
                MMAH16816(o[2 * j + 1], pl[kf], vh4[2], vh4[3]);
            }
        }
    }

    float inv[2] = {1.0f / l_i[0], 1.0f / l_i[1]};
    int row0 = q0 + wm + gid;
#pragma unroll
    for (int nf = 0; nf < 16; nf++) {
        int col = h * HD + nf * 8 + tig * 2;
#pragma unroll
        for (int r = 0; r < 2; r++) {
            float o0 = o[nf][r * 2] * inv[r];
            float o1 = o[nf][r * 2 + 1] * inv[r];
            __half h0 = __float2half(o0), h1 = __float2half(o1);
            float l0 = o0 - __half2float(h0), l1 = o1 - __half2float(h1);
            size_t base = (size_t)(row0 + r * 8) * NQ + col;
            *(__half2*)(Ohi + base) = __halves2half2(h0, h1);
            *(__half2*)(Olo + base) = __halves2half2(__float2half(l0), __float2half(l1));
        }
    }
}

// ---------------- launcher ----------------
extern "C" void kernel_launch(void* const* d_in, const int* in_sizes, int n_in,
                              void* d_out, int out_size) {
    const float* x  = (const float*)d_in[0];
    const float* Wq = (const float*)d_in[1];
    const float* Wk = (const float*)d_in[2];
    const float* Wv = (const float*)d_in[3];
    const float* Wo = (const float*)d_in[4];
    const float* qw = (const float*)d_in[5];
    const float* kw = (const float*)d_in[6];
    float* out = (float*)d_out;

    float *Qb, *Kb;
    cudaGetSymbolAddress((void**)&Qb, g_Q);
    cudaGetSymbolAddress((void**)&Kb, g_K);
    __half *Xhi, *Xlo, *Ohi, *Olo, *Wqkv, *Wot, *Vh;
    cudaGetSymbolAddress((void**)&Xhi, g_Xhi);
    cudaGetSymbolAddress((void**)&Xlo, g_Xlo);
    cudaGetSymbolAddress((void**)&Ohi, g_Ohi);
    cudaGetSymbolAddress((void**)&Olo, g_Olo);
    cudaGetSymbolAddress((void**)&Wqkv, g_Wqkv);
    cudaGetSymbolAddress((void**)&Wot, g_Wot);
    cudaGetSymbolAddress((void**)&Vh, g_Vh);
    __nv_bfloat16 *Qhi, *Qlo, *Khi, *Klo;
    cudaGetSymbolAddress((void**)&Qhi, g_Qhi);
    cudaGetSymbolAddress((void**)&Qlo, g_Qlo);
    cudaGetSymbolAddress((void**)&Khi, g_Khi);
    cudaGetSymbolAddress((void**)&Klo, g_Klo);

    cudaFuncSetAttribute(gemm2_kernel, cudaFuncAttributeMaxDynamicSharedMemorySize, GEMM2_SMEM);
    cudaFuncSetAttribute(attn_kernel, cudaFuncAttributeMaxDynamicSharedMemorySize, ATTN_SMEM);

    // 1. prep
    int n4x = T_SEQ * D_MODEL / 4;
    splith_kernel<<<(n4x + 255) / 256, 256>>>((const float4*)x, Xhi, Xlo, n4x);
    tf16_kernel<<<dim3(NQ / 32, D_MODEL / 32), 256>>>(Wq, Wqkv, NQ, 0);
    tf16_kernel<<<dim3(NKVD / 32, D_MODEL / 32), 256>>>(Wk, Wqkv, NKVD, NQ);
    tf16_kernel<<<dim3(NKVD / 32, D_MODEL / 32), 256>>>(Wv, Wqkv, NKVD, NQ + NKVD);
    tf16_kernel<<<dim3(NQ / 32, D_MODEL / 32), 256>>>(Wo, Wot, NQ, 0);
    rope_lut_kernel<<<T_SEQ, 64>>>();

    // 2. merged QKV projection
    gemm2_kernel<<<dim3(NQKV / GBN, T_SEQ / GBM), 256, GEMM2_SMEM>>>(
        Xhi, Xlo, Wqkv, Qb, Kb, Vh, D_MODEL, 1);

    // 3. RMSNorm + RoPE
    rmsnorm_rope_kernel<<<dim3(T_SEQ, NH + NKV), 128>>>(qw, kw);

    // 4. attention
    attn_kernel<<<dim3(T_SEQ / 64, NH), 128, ATTN_SMEM>>>(Qhi, Qlo, Khi, Klo, Vh, Ohi, Olo);

    // 5. output projection
    gemm2_kernel<<<dim3(D_MODEL / GBN, T_SEQ / GBM), 256, GEMM2_SMEM>>>(
        Ohi, Olo, Wot, out, out, (__half*)Vh, NQ, 0);
}